// round 1
// baseline (speedup 1.0000x reference)
#include <cuda_runtime.h>

// Problem constants
#define NB   4
#define CIN  256
#define HH   128
#define WW   128
#define HWP  (HH*WW)      // 16384
#define CO   512
#define TT   4096         // 64*64 output pixels
#define EPSF 1e-5f
#define ITERS 3

// ---------------------------------------------------------------------------
// Scratch (pixel-major layouts: [B][pixel][channel])
// ---------------------------------------------------------------------------
__device__ float g_k[(size_t)NB*HWP*CO];   // 128 MB  k projection, (B,HW,CO)
__device__ float g_v[(size_t)NB*HWP*CO];   // 128 MB  v projection, (B,HW,CO)
__device__ float g_x[(size_t)NB*TT*CO];    //  32 MB  x_out, (B,T,CO)
__device__ float g_q[(size_t)NB*TT*CO];    //  32 MB  q / mlp / conv staging, (B,T,CO)

__device__ __forceinline__ float warp_sum(float v) {
#pragma unroll
    for (int o = 16; o > 0; o >>= 1) v += __shfl_xor_sync(0xffffffffu, v, o);
    return v;
}

// ---------------------------------------------------------------------------
// Tiled SGEMM: C[b][m][n] = sum_k A(m,k) * Wm[n][k] + bias[n]
//   MODE 0: A is K-major:  A[k][m] = Ab[k*M + m]          (k/v proj from NCHW x_in)
//   MODE 1: A is M-major:  A[m][k] = Ab[m*K + k]          (q / mlp from g_x)
//   MODE 2: conv gather:   A[(c,w)][t] = x_in[b][c][pix(w,t)]  (implicit im2col)
// N is always CO (=512). Per-batch A stride = M*K for all modes.
// Tile 128x128, K-chunk 16, 256 threads, 8x8 per-thread microtile.
// ---------------------------------------------------------------------------
template<int MODE>
__global__ __launch_bounds__(256)
void gemm_kernel(const float* __restrict__ A, const float* __restrict__ Wm,
                 const float* __restrict__ bias, float* __restrict__ C,
                 int M, int K)
{
    __shared__ float As[16][132];
    __shared__ float Bs[16][132];

    const int m0 = blockIdx.x * 128;
    const int n0 = blockIdx.y * 128;
    const int b  = blockIdx.z;
    const int tid = threadIdx.x;
    const int tx = tid & 15, ty = tid >> 4;

    const float* Ab = A + (size_t)b * M * K;

    float acc[8][8];
#pragma unroll
    for (int i = 0; i < 8; i++)
#pragma unroll
        for (int j = 0; j < 8; j++) acc[i][j] = 0.f;

    for (int k0 = 0; k0 < K; k0 += 16) {
        // ---- load A tile (16 k x 128 m) ----
        if (MODE == 0) {
#pragma unroll
            for (int i = 0; i < 2; i++) {
                int l  = tid + i * 256;            // 0..511 float4 slots
                int r  = l >> 5;                   // k row 0..15
                int c4 = (l & 31) << 2;            // m col
                float4 v = *(const float4*)&Ab[(size_t)(k0 + r) * M + m0 + c4];
                *(float4*)&As[r][c4] = v;
            }
        } else if (MODE == 1) {
#pragma unroll
            for (int i = 0; i < 2; i++) {
                int l  = tid + i * 256;
                int r  = l >> 2;                   // m row 0..127
                int c4 = (l & 3) << 2;             // k col
                float4 v = *(const float4*)&Ab[(size_t)(m0 + r) * K + k0 + c4];
                As[c4 + 0][r] = v.x; As[c4 + 1][r] = v.y;
                As[c4 + 2][r] = v.z; As[c4 + 3][r] = v.w;
            }
        } else { // MODE 2: conv im2col gather
#pragma unroll
            for (int i = 0; i < 8; i++) {
                int l = tid + i * 256;             // 0..2047 scalars
                int r = l >> 7;                    // k row 0..15
                int m = l & 127;                   // t col
                int kg = k0 + r;
                int c  = kg >> 2, w = kg & 3;      // channel, window pos (kh*2+kw)
                int t  = m0 + m;
                int ho = t >> 6, wo = t & 63;
                int pix = ((ho << 1) + (w >> 1)) * WW + (wo << 1) + (w & 1);
                As[r][m] = Ab[(size_t)c * HWP + pix];
            }
        }
        // ---- load B tile: Wm[n][k], 128 n x 16 k ----
#pragma unroll
        for (int i = 0; i < 2; i++) {
            int l  = tid + i * 256;
            int r  = l >> 2;                       // n row 0..127
            int c4 = (l & 3) << 2;                 // k col
            float4 v = *(const float4*)&Wm[(size_t)(n0 + r) * K + k0 + c4];
            Bs[c4 + 0][r] = v.x; Bs[c4 + 1][r] = v.y;
            Bs[c4 + 2][r] = v.z; Bs[c4 + 3][r] = v.w;
        }
        __syncthreads();

#pragma unroll
        for (int kk = 0; kk < 16; kk++) {
            float a[8], bb[8];
            *(float4*)&a[0]  = *(const float4*)&As[kk][ty * 8];
            *(float4*)&a[4]  = *(const float4*)&As[kk][ty * 8 + 4];
            *(float4*)&bb[0] = *(const float4*)&Bs[kk][tx * 8];
            *(float4*)&bb[4] = *(const float4*)&Bs[kk][tx * 8 + 4];
#pragma unroll
            for (int i = 0; i < 8; i++)
#pragma unroll
                for (int j = 0; j < 8; j++)
                    acc[i][j] += a[i] * bb[j];
        }
        __syncthreads();
    }

    float bv[8];
#pragma unroll
    for (int j = 0; j < 8; j++) bv[j] = bias[n0 + tx * 8 + j];

#pragma unroll
    for (int i = 0; i < 8; i++) {
        size_t o = ((size_t)b * M + m0 + ty * 8 + i) * CO + n0 + tx * 8;
        float4 w0 = make_float4(acc[i][0] + bv[0], acc[i][1] + bv[1],
                                acc[i][2] + bv[2], acc[i][3] + bv[3]);
        float4 w1 = make_float4(acc[i][4] + bv[4], acc[i][5] + bv[5],
                                acc[i][6] + bv[6], acc[i][7] + bv[7]);
        *(float4*)&C[o]     = w0;
        *(float4*)&C[o + 4] = w1;
    }
}

// ---------------------------------------------------------------------------
// Channel LayerNorm over CO=512 (contiguous row). One block per (b,t).
// add=0: xo = LN(in);  add=1: xo += LN(in)
// ---------------------------------------------------------------------------
__global__ __launch_bounds__(256)
void ln_kernel(const float* __restrict__ in, float* __restrict__ xo,
               const float* __restrict__ g, const float* __restrict__ bvec, int add)
{
    const int tid = threadIdx.x;
    const size_t row = blockIdx.x;
    const float* r = in + row * CO;
    float v0 = r[tid], v1 = r[tid + 256];
    float s  = v0 + v1;
    float s2 = v0 * v0 + v1 * v1;
    s  = warp_sum(s);
    s2 = warp_sum(s2);
    __shared__ float r1[8], r2[8];
    const int lane = tid & 31, warp = tid >> 5;
    if (lane == 0) { r1[warp] = s; r2[warp] = s2; }
    __syncthreads();
    float ss = 0.f, sq = 0.f;
#pragma unroll
    for (int i = 0; i < 8; i++) { ss += r1[i]; sq += r2[i]; }
    float mu  = ss / CO;
    float var = sq / CO - mu * mu;
    float rs  = rsqrtf(var + EPSF);
    float o0 = (v0 - mu) * rs * g[tid]       + bvec[tid];
    float o1 = (v1 - mu) * rs * g[tid + 256] + bvec[tid + 256];
    float* xr = xo + row * CO;
    if (add) { xr[tid] += o0; xr[tid + 256] += o1; }
    else     { xr[tid]  = o0; xr[tid + 256]  = o1; }
}

// ---------------------------------------------------------------------------
// Fused attention step: per (b,t) block
//   att[w] = softmax_w( k[b, pix(w,t), :] . q[b,t,:] )
//   upd[f] = sum_w att[w] * v[b, pix(w,t), f]
//   x_out[b,t,:] += LN_channel(upd) * lnv_g + lnv_b
// ---------------------------------------------------------------------------
__global__ __launch_bounds__(256)
void att_kernel(const float* __restrict__ qb, const float* __restrict__ kb,
                const float* __restrict__ vb, float* __restrict__ xb,
                const float* __restrict__ lg, const float* __restrict__ lb)
{
    const int tid = threadIdx.x;
    const int row = blockIdx.x;            // b*T + t
    const int b = row >> 12;
    const int t = row & (TT - 1);
    const int ho = t >> 6, wo = t & 63;
    const int pix0 = (ho << 1) * WW + (wo << 1);
    const size_t base = ((size_t)b * HWP + pix0) * CO;
    const float* kp = kb + base;
    const float* vp = vb + base;
    const float* qr = qb + (size_t)row * CO;

    const size_t S1 = CO;                  // (kh,kw)=(0,1)
    const size_t S2 = (size_t)WW * CO;     // (1,0)
    const size_t S3 = S2 + CO;             // (1,1)

    float q0 = qr[tid], q1 = qr[tid + 256];
    float d0 = q0 * kp[tid]      + q1 * kp[tid + 256];
    float d1 = q0 * kp[S1 + tid] + q1 * kp[S1 + tid + 256];
    float d2 = q0 * kp[S2 + tid] + q1 * kp[S2 + tid + 256];
    float d3 = q0 * kp[S3 + tid] + q1 * kp[S3 + tid + 256];
    d0 = warp_sum(d0); d1 = warp_sum(d1); d2 = warp_sum(d2); d3 = warp_sum(d3);

    __shared__ float red[4][8];
    __shared__ float r1[8], r2[8];
    const int lane = tid & 31, warp = tid >> 5;
    if (lane == 0) { red[0][warp] = d0; red[1][warp] = d1;
                     red[2][warp] = d2; red[3][warp] = d3; }
    __syncthreads();
    float a0 = 0.f, a1 = 0.f, a2 = 0.f, a3 = 0.f;
#pragma unroll
    for (int i = 0; i < 8; i++) {
        a0 += red[0][i]; a1 += red[1][i]; a2 += red[2][i]; a3 += red[3][i];
    }
    float mx = fmaxf(fmaxf(a0, a1), fmaxf(a2, a3));
    float e0 = __expf(a0 - mx), e1 = __expf(a1 - mx);
    float e2 = __expf(a2 - mx), e3 = __expf(a3 - mx);
    float inv = 1.f / (e0 + e1 + e2 + e3);
    e0 *= inv; e1 *= inv; e2 *= inv; e3 *= inv;

    float u0 = e0 * vp[tid]       + e1 * vp[S1 + tid]
             + e2 * vp[S2 + tid]  + e3 * vp[S3 + tid];
    float u1 = e0 * vp[tid + 256]      + e1 * vp[S1 + tid + 256]
             + e2 * vp[S2 + tid + 256] + e3 * vp[S3 + tid + 256];

    float s  = u0 + u1;
    float s2 = u0 * u0 + u1 * u1;
    s  = warp_sum(s);
    s2 = warp_sum(s2);
    if (lane == 0) { r1[warp] = s; r2[warp] = s2; }
    __syncthreads();
    float ss = 0.f, sq = 0.f;
#pragma unroll
    for (int i = 0; i < 8; i++) { ss += r1[i]; sq += r2[i]; }
    float mu  = ss / CO;
    float var = sq / CO - mu * mu;
    float rs  = rsqrtf(var + EPSF);

    float* xo = xb + (size_t)row * CO;
    xo[tid]       += (u0 - mu) * rs * lg[tid]       + lb[tid];
    xo[tid + 256] += (u1 - mu) * rs * lg[tid + 256] + lb[tid + 256];
}

// ---------------------------------------------------------------------------
// Final transpose (B,T,CO) pixel-major -> NCHW output (B,CO,64,64)
// ---------------------------------------------------------------------------
__global__ void transpose_kernel(const float* __restrict__ x, float* __restrict__ out)
{
    __shared__ float tile[32][33];
    const int b  = blockIdx.z;
    const int t0 = blockIdx.x * 32;
    const int f0 = blockIdx.y * 32;
    const int tx = threadIdx.x, ty = threadIdx.y;
#pragma unroll
    for (int j = 0; j < 32; j += 8)
        tile[ty + j][tx] = x[((size_t)b * TT + t0 + ty + j) * CO + f0 + tx];
    __syncthreads();
#pragma unroll
    for (int j = 0; j < 32; j += 8)
        out[((size_t)b * CO + f0 + ty + j) * TT + t0 + tx] = tile[tx][ty + j];
}

// ---------------------------------------------------------------------------
extern "C" void kernel_launch(void* const* d_in, const int* in_sizes, int n_in,
                              void* d_out, int out_size)
{
    const float* x_in   = (const float*)d_in[0];
    const float* conv_w = (const float*)d_in[1];
    const float* conv_b = (const float*)d_in[2];
    const float* k_w    = (const float*)d_in[3];
    const float* k_b    = (const float*)d_in[4];
    const float* q_w    = (const float*)d_in[5];
    const float* q_b    = (const float*)d_in[6];
    const float* v_w    = (const float*)d_in[7];
    const float* v_b    = (const float*)d_in[8];
    const float* mlp_w  = (const float*)d_in[9];
    const float* mlp_b  = (const float*)d_in[10];
    const float* lnc_g  = (const float*)d_in[11];
    const float* lnc_b  = (const float*)d_in[12];
    const float* lnv_g  = (const float*)d_in[13];
    const float* lnv_b  = (const float*)d_in[14];
    const float* lnm_g  = (const float*)d_in[15];
    const float* lnm_b  = (const float*)d_in[16];
    float* out = (float*)d_out;

    float *pk, *pv, *px, *pq;
    cudaGetSymbolAddress((void**)&pk, g_k);
    cudaGetSymbolAddress((void**)&pv, g_v);
    cudaGetSymbolAddress((void**)&px, g_x);
    cudaGetSymbolAddress((void**)&pq, g_q);

    // 1) patchify conv (implicit im2col GEMM) -> staging, then channel LN -> x_out
    gemm_kernel<2><<<dim3(TT / 128, CO / 128, NB), 256>>>(x_in, conv_w, conv_b, pq, TT, CIN * 4);
    ln_kernel<<<NB * TT, 256>>>(pq, px, lnc_g, lnc_b, 0);

    // 2) k, v projections at full resolution (K-major A = NCHW x_in directly)
    gemm_kernel<0><<<dim3(HWP / 128, CO / 128, NB), 256>>>(x_in, k_w, k_b, pk, HWP, CIN);
    gemm_kernel<0><<<dim3(HWP / 128, CO / 128, NB), 256>>>(x_in, v_w, v_b, pv, HWP, CIN);

    // 3) iterative grouping
    for (int it = 0; it < ITERS; it++) {
        gemm_kernel<1><<<dim3(TT / 128, CO / 128, NB), 256>>>(px, q_w, q_b, pq, TT, CO);
        att_kernel<<<NB * TT, 256>>>(pq, pk, pv, px, lnv_g, lnv_b);
        gemm_kernel<1><<<dim3(TT / 128, CO / 128, NB), 256>>>(px, mlp_w, mlp_b, pq, TT, CO);
        ln_kernel<<<NB * TT, 256>>>(pq, px, lnm_g, lnm_b, 1);
    }

    // 4) pixel-major -> NCHW output
    transpose_kernel<<<dim3(TT / 32, CO / 32, NB), dim3(32, 8)>>>(px, out);
}

// round 3
// speedup vs baseline: 1.8649x; 1.8649x over previous
#include <cuda_runtime.h>
#include <cuda_fp16.h>
#include <cstdint>

// Problem constants
#define NB   4
#define CIN  256
#define HH   128
#define WW   128
#define HWP  (HH*WW)      // 16384
#define CO   512
#define TT   4096         // 64*64 output pixels
#define EPSF 1e-5f
#define ITERS 3

// ---------------------------------------------------------------------------
// Scratch (pixel-major layouts: [B][pixel][channel])
// ---------------------------------------------------------------------------
__device__ float g_k[(size_t)NB*HWP*CO];   // 128 MB  k projection, (B,HW,CO)
__device__ float g_v[(size_t)NB*HWP*CO];   // 128 MB  v projection, (B,HW,CO)
__device__ float g_x[(size_t)NB*TT*CO];    //  32 MB  x_out, (B,T,CO)
__device__ float g_q[(size_t)NB*TT*CO];    //  32 MB  q / mlp / conv staging, (B,T,CO)

// ===========================================================================
// helpers
// ===========================================================================
__device__ __forceinline__ uint32_t smem_to_u32(const void* p) {
    uint32_t a;
    asm("{ .reg .u64 t; cvta.to.shared.u64 t, %1; cvt.u32.u64 %0, t; }"
        : "=r"(a) : "l"(p));
    return a;
}
__device__ __forceinline__ float warp_sum(float v) {
#pragma unroll
    for (int o = 16; o > 0; o >>= 1) v += __shfl_xor_sync(0xffffffffu, v, o);
    return v;
}
__device__ __forceinline__ void mma16816(float* c, const uint32_t* a, const uint32_t* b) {
    asm volatile("mma.sync.aligned.m16n8k16.row.col.f32.f16.f16.f32 "
        "{%0,%1,%2,%3}, {%4,%5,%6,%7}, {%8,%9}, {%0,%1,%2,%3};"
        : "+f"(c[0]), "+f"(c[1]), "+f"(c[2]), "+f"(c[3])
        : "r"(a[0]), "r"(a[1]), "r"(a[2]), "r"(a[3]), "r"(b[0]), "r"(b[1]));
}
__device__ __forceinline__ void ldsm4(uint32_t* r, uint32_t a) {
    asm volatile("ldmatrix.sync.aligned.m8n8.x4.shared.b16 {%0,%1,%2,%3}, [%4];"
        : "=r"(r[0]), "=r"(r[1]), "=r"(r[2]), "=r"(r[3]) : "r"(a));
}
__device__ __forceinline__ void ldsm4t(uint32_t* r, uint32_t a) {
    asm volatile("ldmatrix.sync.aligned.m8n8.x4.trans.shared.b16 {%0,%1,%2,%3}, [%4];"
        : "=r"(r[0]), "=r"(r[1]), "=r"(r[2]), "=r"(r[3]) : "r"(a));
}
__device__ __forceinline__ void sts128u(uint32_t a, uint4 v) {
    asm volatile("st.shared.v4.b32 [%0], {%1,%2,%3,%4};"
        :: "r"(a), "r"(v.x), "r"(v.y), "r"(v.z), "r"(v.w) : "memory");
}
__device__ __forceinline__ void sts16(uint32_t a, uint16_t v) {
    asm volatile("st.shared.b16 [%0], %1;" :: "r"(a), "h"(v) : "memory");
}
__device__ __forceinline__ uint32_t packh2(__half a, __half b) {
    __half2 t = __halves2half2(a, b);
    return *reinterpret_cast<uint32_t*>(&t);
}
// split 8 fp32 -> 8 fp16 hi (uint4) + 8 fp16 lo (uint4)
__device__ __forceinline__ void split8(const float* f, uint4& H, uint4& L) {
    __half hh[8], ll[8];
#pragma unroll
    for (int i = 0; i < 8; i++) {
        hh[i] = __float2half_rn(f[i]);
        ll[i] = __float2half_rn(f[i] - __half2float(hh[i]));
    }
    H = make_uint4(packh2(hh[0],hh[1]), packh2(hh[2],hh[3]),
                   packh2(hh[4],hh[5]), packh2(hh[6],hh[7]));
    L = make_uint4(packh2(ll[0],ll[1]), packh2(ll[2],ll[3]),
                   packh2(ll[4],ll[5]), packh2(ll[6],ll[7]));
}
__device__ __forceinline__ void split1(float x, uint16_t& h, uint16_t& l) {
    __half hh = __float2half_rn(x);
    __half ll = __float2half_rn(x - __half2float(hh));
    h = *reinterpret_cast<uint16_t*>(&hh);
    l = *reinterpret_cast<uint16_t*>(&ll);
}

// ===========================================================================
// HMMA split-fp16 GEMM: C[b][m][n] = sum_k A(m,k)*Wm[n][k] + bias[n]
//   MODE 0: A K-major  A[k][m]   (k/v proj from NCHW x_in)
//   MODE 1: A M-major  A[m][k]   (q / mlp from g_x)
//   MODE 2: conv im2col gather from NCHW x_in
// Tile 128x128, K-chunk 32 fp32, 8 warps (2x4), warp tile 64x32,
// mma.m16n8k16, 3-term split (hi*hi + hi*lo + lo*hi), double-buffered smem.
// SMEM layout (per stage, 32KB):
//   A (MODE1/2): 128 rows x 128B, row = [hi 32 fp16 | lo 32 fp16], chunk^(row&7) swizzle
//   A (MODE0)  : 32 k-rows x 256B hi (8KB) then lo (8KB), chunk^(k&7) swizzle
//   B          : 128 n-rows x 128B, hi|lo interleaved like MODE1 A
// ===========================================================================
#define STAGE   32768
#define SMEMDYN (2*STAGE)

template<int MODE>
__global__ __launch_bounds__(256, 1)
void hgemm(const float* __restrict__ A, const float* __restrict__ Wm,
           const float* __restrict__ bias, float* __restrict__ C,
           int M, int K)
{
    extern __shared__ char sm_[];
    const uint32_t sb = smem_to_u32(sm_);
    const int tid = threadIdx.x;
    const int lane = tid & 31;
    const int wid = tid >> 5;
    const int wm = wid & 1, wn = wid >> 1;
    const int m0 = blockIdx.x * 128, n0 = blockIdx.y * 128, bz = blockIdx.z;
    const float* Ab = A + (size_t)bz * M * K;

    float acc[4][4][4];
#pragma unroll
    for (int i = 0; i < 4; i++)
#pragma unroll
        for (int j = 0; j < 4; j++)
#pragma unroll
            for (int r = 0; r < 4; r++) acc[i][j][r] = 0.f;

    // ---- per-thread load bases ----
    const float* pB = Wm + (size_t)(n0 + (tid >> 1)) * K + (tid & 1) * 16;
    const float* pA = Ab;
    int pixA = 0, pixB = 0;
    if (MODE == 1) {
        pA = Ab + (size_t)(m0 + (tid >> 1)) * K + (tid & 1) * 16;
    } else if (MODE == 0) {
        pA = Ab + (size_t)(tid >> 3) * M + m0 + (tid & 7) * 16;
    } else {
        int m = tid & 127, t0 = tid >> 7;
        int tg = m0 + m, ho = tg >> 6, wo = tg & 63;
        pixA = ((ho << 1) + (t0 >> 1)) * WW + (wo << 1) + (t0 & 1);
        int w2 = t0 + 2;
        pixB = ((ho << 1) + (w2 >> 1)) * WW + (wo << 1) + (w2 & 1);
    }

    float fa[16], fb[16];
    const int nch = K / 32;

    auto loadCh = [&](int c) {
#pragma unroll
        for (int i = 0; i < 4; i++)
            *(float4*)&fb[i * 4] = *(const float4*)(pB + (size_t)c * 32 + i * 4);
        if (MODE == 1) {
#pragma unroll
            for (int i = 0; i < 4; i++)
                *(float4*)&fa[i * 4] = *(const float4*)(pA + (size_t)c * 32 + i * 4);
        } else if (MODE == 0) {
#pragma unroll
            for (int i = 0; i < 4; i++)
                *(float4*)&fa[i * 4] = *(const float4*)(pA + (size_t)c * 32 * M + i * 4);
        } else {
#pragma unroll
            for (int i = 0; i < 16; i++) {
                int cch = c * 8 + (i >> 1);
                fa[i] = __ldg(pA + (size_t)cch * HWP + ((i & 1) ? pixB : pixA));
            }
        }
    };

    auto storeCh = [&](int s) {
        const uint32_t As = sb + s * STAGE;
        const uint32_t Bs = As + 16384;
        {   // B tile
            int n = tid >> 1, cb = (tid & 1) * 2;
            uint32_t ra = Bs + n * 128;
            uint32_t xr = n & 7;
#pragma unroll
            for (int j = 0; j < 2; j++) {
                uint4 H, L; split8(&fb[j * 8], H, L);
                sts128u(ra + (((cb + j) ^ xr) << 4), H);
                sts128u(ra + (((cb + j + 4) ^ xr) << 4), L);
            }
        }
        if (MODE == 1) {
            int m = tid >> 1, cb = (tid & 1) * 2;
            uint32_t ra = As + m * 128;
            uint32_t xr = m & 7;
#pragma unroll
            for (int j = 0; j < 2; j++) {
                uint4 H, L; split8(&fa[j * 8], H, L);
                sts128u(ra + (((cb + j) ^ xr) << 4), H);
                sts128u(ra + (((cb + j + 4) ^ xr) << 4), L);
            }
        } else if (MODE == 0) {
            int k = tid >> 3, cb = (tid & 7) * 2;
            uint32_t rh = As + k * 256;
            uint32_t xr = k & 7;
#pragma unroll
            for (int j = 0; j < 2; j++) {
                uint4 H, L; split8(&fa[j * 8], H, L);
                sts128u(rh + (((cb + j) ^ xr) << 4), H);
                sts128u(rh + 8192 + (((cb + j) ^ xr) << 4), L);
            }
        } else {
            int m = tid & 127, t0 = tid >> 7;
            uint32_t ra = As + m * 128;
            uint32_t xr = m & 7;
#pragma unroll
            for (int i = 0; i < 16; i++) {
                int kk = t0 + 2 * i;
                uint16_t h, l; split1(fa[i], h, l);
                uint32_t byt = (kk & 7) * 2;
                sts16(ra + (((kk >> 3) ^ xr) << 4) + byt, h);
                sts16(ra + ((((kk >> 3) + 4) ^ xr) << 4) + byt, l);
            }
        }
    };

    auto computeCh = [&](int s) {
        const uint32_t As = sb + s * STAGE;
        const uint32_t Bs = As + 16384;
        const int g = lane >> 3;
        const uint32_t l7 = lane & 7;
#pragma unroll
        for (int ks = 0; ks < 2; ++ks) {
            uint32_t bh[8], bl[8];
            {
                uint32_t nrow = wn * 32 + (g >> 1) * 8 + l7;
                uint32_t cH = ((ks * 2 + (g & 1)) ^ l7) << 4;
                uint32_t cL = ((ks * 2 + (g & 1) + 4) ^ l7) << 4;
                uint32_t r0 = Bs + nrow * 128;
                ldsm4(&bh[0], r0 + cH);
                ldsm4(&bl[0], r0 + cL);
                uint32_t r1 = r0 + 16 * 128;
                ldsm4(&bh[4], r1 + cH);
                ldsm4(&bl[4], r1 + cL);
            }
#pragma unroll
            for (int mt = 0; mt < 4; ++mt) {
                uint32_t ah[4], al[4];
                if (MODE == 0) {
                    uint32_t krow = ks * 16 + (g >> 1) * 8 + l7;
                    uint32_t mch = wm * 8 + mt * 2 + (g & 1);
                    uint32_t a = As + krow * 256 + ((mch ^ l7) << 4);
                    ldsm4t(ah, a);
                    ldsm4t(al, a + 8192);
                } else {
                    uint32_t mrow = wm * 64 + mt * 16 + (g & 1) * 8 + l7;
                    uint32_t ch = ks * 2 + (g >> 1);
                    uint32_t ra = As + mrow * 128;
                    ldsm4(ah, ra + ((ch ^ l7) << 4));
                    ldsm4(al, ra + (((ch + 4) ^ l7) << 4));
                }
#pragma unroll
                for (int nt = 0; nt < 4; ++nt) {
                    mma16816(acc[mt][nt], ah, &bh[nt * 2]);
                    mma16816(acc[mt][nt], ah, &bl[nt * 2]);
                    mma16816(acc[mt][nt], al, &bh[nt * 2]);
                }
            }
        }
    };

    loadCh(0);
    storeCh(0);
    __syncthreads();
    for (int c = 0; c < nch; ++c) {
        if (c + 1 < nch) loadCh(c + 1);
        computeCh(c & 1);
        if (c + 1 < nch) storeCh((c + 1) & 1);
        __syncthreads();
    }

    // ---- epilogue ----
    const int gq = lane >> 2, tq = lane & 3;
#pragma unroll
    for (int mt = 0; mt < 4; ++mt) {
        int mrow = m0 + wm * 64 + mt * 16 + gq;
        float* Cr = C + ((size_t)bz * M + mrow) * CO + n0;
#pragma unroll
        for (int nt = 0; nt < 4; ++nt) {
            int col = wn * 32 + nt * 8 + tq * 2;
            float b0 = bias[n0 + col], b1 = bias[n0 + col + 1];
            float2 v0; v0.x = acc[mt][nt][0] + b0; v0.y = acc[mt][nt][1] + b1;
            *(float2*)&Cr[col] = v0;
            float2 v1; v1.x = acc[mt][nt][2] + b0; v1.y = acc[mt][nt][3] + b1;
            *(float2*)&Cr[col + 8 * CO] = v1;
        }
    }
}

// ---------------------------------------------------------------------------
// Channel LayerNorm over CO=512 (contiguous row). One block per (b,t).
// ---------------------------------------------------------------------------
__global__ __launch_bounds__(256)
void ln_kernel(const float* __restrict__ in, float* __restrict__ xo,
               const float* __restrict__ g, const float* __restrict__ bvec, int add)
{
    const int tid = threadIdx.x;
    const size_t row = blockIdx.x;
    const float* r = in + row * CO;
    float v0 = r[tid], v1 = r[tid + 256];
    float s  = v0 + v1;
    float s2 = v0 * v0 + v1 * v1;
    s  = warp_sum(s);
    s2 = warp_sum(s2);
    __shared__ float r1[8], r2[8];
    const int lane = tid & 31, warp = tid >> 5;
    if (lane == 0) { r1[warp] = s; r2[warp] = s2; }
    __syncthreads();
    float ss = 0.f, sq = 0.f;
#pragma unroll
    for (int i = 0; i < 8; i++) { ss += r1[i]; sq += r2[i]; }
    float mu  = ss / CO;
    float var = sq / CO - mu * mu;
    float rs  = rsqrtf(var + EPSF);
    float o0 = (v0 - mu) * rs * g[tid]       + bvec[tid];
    float o1 = (v1 - mu) * rs * g[tid + 256] + bvec[tid + 256];
    float* xr = xo + row * CO;
    if (add) { xr[tid] += o0; xr[tid + 256] += o1; }
    else     { xr[tid]  = o0; xr[tid + 256]  = o1; }
}

// ---------------------------------------------------------------------------
// Fused attention step: per (b,t) block
// ---------------------------------------------------------------------------
__global__ __launch_bounds__(256)
void att_kernel(const float* __restrict__ qb, const float* __restrict__ kb,
                const float* __restrict__ vb, float* __restrict__ xb,
                const float* __restrict__ lg, const float* __restrict__ lb)
{
    const int tid = threadIdx.x;
    const int row = blockIdx.x;            // b*T + t
    const int b = row >> 12;
    const int t = row & (TT - 1);
    const int ho = t >> 6, wo = t & 63;
    const int pix0 = (ho << 1) * WW + (wo << 1);
    const size_t base = ((size_t)b * HWP + pix0) * CO;
    const float* kp = kb + base;
    const float* vp = vb + base;
    const float* qr = qb + (size_t)row * CO;

    const size_t S1 = CO;
    const size_t S2 = (size_t)WW * CO;
    const size_t S3 = S2 + CO;

    float q0 = qr[tid], q1 = qr[tid + 256];
    float d0 = q0 * kp[tid]      + q1 * kp[tid + 256];
    float d1 = q0 * kp[S1 + tid] + q1 * kp[S1 + tid + 256];
    float d2 = q0 * kp[S2 + tid] + q1 * kp[S2 + tid + 256];
    float d3 = q0 * kp[S3 + tid] + q1 * kp[S3 + tid + 256];
    d0 = warp_sum(d0); d1 = warp_sum(d1); d2 = warp_sum(d2); d3 = warp_sum(d3);

    __shared__ float red[4][8];
    __shared__ float r1[8], r2[8];
    const int lane = tid & 31, warp = tid >> 5;
    if (lane == 0) { red[0][warp] = d0; red[1][warp] = d1;
                     red[2][warp] = d2; red[3][warp] = d3; }
    __syncthreads();
    float a0 = 0.f, a1 = 0.f, a2 = 0.f, a3 = 0.f;
#pragma unroll
    for (int i = 0; i < 8; i++) {
        a0 += red[0][i]; a1 += red[1][i]; a2 += red[2][i]; a3 += red[3][i];
    }
    float mx = fmaxf(fmaxf(a0, a1), fmaxf(a2, a3));
    float e0 = __expf(a0 - mx), e1 = __expf(a1 - mx);
    float e2 = __expf(a2 - mx), e3 = __expf(a3 - mx);
    float inv = 1.f / (e0 + e1 + e2 + e3);
    e0 *= inv; e1 *= inv; e2 *= inv; e3 *= inv;

    float u0 = e0 * vp[tid]       + e1 * vp[S1 + tid]
             + e2 * vp[S2 + tid]  + e3 * vp[S3 + tid];
    float u1 = e0 * vp[tid + 256]      + e1 * vp[S1 + tid + 256]
             + e2 * vp[S2 + tid + 256] + e3 * vp[S3 + tid + 256];

    float s  = u0 + u1;
    float s2 = u0 * u0 + u1 * u1;
    s  = warp_sum(s);
    s2 = warp_sum(s2);
    if (lane == 0) { r1[warp] = s; r2[warp] = s2; }
    __syncthreads();
    float ss = 0.f, sq = 0.f;
#pragma unroll
    for (int i = 0; i < 8; i++) { ss += r1[i]; sq += r2[i]; }
    float mu  = ss / CO;
    float var = sq / CO - mu * mu;
    float rs  = rsqrtf(var + EPSF);

    float* xo = xb + (size_t)row * CO;
    xo[tid]       += (u0 - mu) * rs * lg[tid]       + lb[tid];
    xo[tid + 256] += (u1 - mu) * rs * lg[tid + 256] + lb[tid + 256];
}

// ---------------------------------------------------------------------------
// Final transpose (B,T,CO) pixel-major -> NCHW output (B,CO,64,64)
// ---------------------------------------------------------------------------
__global__ void transpose_kernel(const float* __restrict__ x, float* __restrict__ out)
{
    __shared__ float tile[32][33];
    const int b  = blockIdx.z;
    const int t0 = blockIdx.x * 32;
    const int f0 = blockIdx.y * 32;
    const int tx = threadIdx.x, ty = threadIdx.y;
#pragma unroll
    for (int j = 0; j < 32; j += 8)
        tile[ty + j][tx] = x[((size_t)b * TT + t0 + ty + j) * CO + f0 + tx];
    __syncthreads();
#pragma unroll
    for (int j = 0; j < 32; j += 8)
        out[((size_t)b * CO + f0 + ty + j) * TT + t0 + tx] = tile[tx][ty + j];
}

// ---------------------------------------------------------------------------
extern "C" void kernel_launch(void* const* d_in, const int* in_sizes, int n_in,
                              void* d_out, int out_size)
{
    const float* x_in   = (const float*)d_in[0];
    const float* conv_w = (const float*)d_in[1];
    const float* conv_b = (const float*)d_in[2];
    const float* k_w    = (const float*)d_in[3];
    const float* k_b    = (const float*)d_in[4];
    const float* q_w    = (const float*)d_in[5];
    const float* q_b    = (const float*)d_in[6];
    const float* v_w    = (const float*)d_in[7];
    const float* v_b    = (const float*)d_in[8];
    const float* mlp_w  = (const float*)d_in[9];
    const float* mlp_b  = (const float*)d_in[10];
    const float* lnc_g  = (const float*)d_in[11];
    const float* lnc_b  = (const float*)d_in[12];
    const float* lnv_g  = (const float*)d_in[13];
    const float* lnv_b  = (const float*)d_in[14];
    const float* lnm_g  = (const float*)d_in[15];
    const float* lnm_b  = (const float*)d_in[16];
    float* out = (float*)d_out;

    float *pk, *pv, *px, *pq;
    cudaGetSymbolAddress((void**)&pk, g_k);
    cudaGetSymbolAddress((void**)&pv, g_v);
    cudaGetSymbolAddress((void**)&px, g_x);
    cudaGetSymbolAddress((void**)&pq, g_q);

    cudaFuncSetAttribute(hgemm<0>, cudaFuncAttributeMaxDynamicSharedMemorySize, SMEMDYN);
    cudaFuncSetAttribute(hgemm<1>, cudaFuncAttributeMaxDynamicSharedMemorySize, SMEMDYN);
    cudaFuncSetAttribute(hgemm<2>, cudaFuncAttributeMaxDynamicSharedMemorySize, SMEMDYN);

    const dim3 gq(TT / 128, CO / 128, NB);     // q/mlp/conv GEMMs
    const dim3 gkv(HWP / 128, CO / 128, NB);   // k/v GEMMs

    // 1) patchify conv (implicit im2col GEMM) -> staging, then channel LN -> x_out
    hgemm<2><<<gq, 256, SMEMDYN>>>(x_in, conv_w, conv_b, pq, TT, CIN * 4);
    ln_kernel<<<NB * TT, 256>>>(pq, px, lnc_g, lnc_b, 0);

    // 2) k, v projections at full resolution
    hgemm<0><<<gkv, 256, SMEMDYN>>>(x_in, k_w, k_b, pk, HWP, CIN);
    hgemm<0><<<gkv, 256, SMEMDYN>>>(x_in, v_w, v_b, pv, HWP, CIN);

    // 3) iterative grouping
    for (int it = 0; it < ITERS; it++) {
        hgemm<1><<<gq, 256, SMEMDYN>>>(px, q_w, q_b, pq, TT, CO);
        att_kernel<<<NB * TT, 256>>>(pq, pk, pv, px, lnv_g, lnv_b);
        hgemm<1><<<gq, 256, SMEMDYN>>>(px, mlp_w, mlp_b, pq, TT, CO);
        ln_kernel<<<NB * TT, 256>>>(pq, px, lnm_g, lnm_b, 1);
    }

    // 4) pixel-major -> NCHW output
    transpose_kernel<<<dim3(TT / 32, CO / 32, NB), dim3(32, 8)>>>(px, out);
}

// round 4
// speedup vs baseline: 2.2622x; 1.2130x over previous
#include <cuda_runtime.h>
#include <cuda_fp16.h>
#include <cstdint>

// Problem constants
#define NB   4
#define CIN  256
#define HH   128
#define WW   128
#define HWP  (HH*WW)      // 16384
#define CO   512
#define TT   4096         // 64*64 output pixels
#define EPSF 1e-5f
#define ITERS 3

// ---------------------------------------------------------------------------
// Scratch
// ---------------------------------------------------------------------------
__device__ float g_k[(size_t)NB*HWP*CO];   // 128 MB  k projection, (B,HW,CO) fp32
__device__ float g_v[(size_t)NB*HWP*CO];   // 128 MB  v projection
__device__ float g_x[(size_t)NB*TT*CO];    //  32 MB  x_out, (B,T,CO) fp32
__device__ float g_q[(size_t)NB*TT*CO];    //  32 MB  q / mlp / conv staging

// fp16 split operands
__device__ __align__(16) __half g_ih[(size_t)NB*CIN*HWP];   // x_in hi, K-major [b][c][pix]
__device__ __align__(16) __half g_il[(size_t)NB*CIN*HWP];   // x_in lo
__device__ __align__(16) __half g_ch[(size_t)NB*1024*TT];   // im2col x_in hi [b][c*4+w][t]
__device__ __align__(16) __half g_cl[(size_t)NB*1024*TT];   // im2col lo
__device__ __align__(16) __half g_xh[(size_t)NB*TT*CO];     // x_out hi, M-major [b][t][c]
__device__ __align__(16) __half g_xl[(size_t)NB*TT*CO];     // x_out lo
#define OFF_CONV 0
#define OFF_K    (512*1024)
#define OFF_Q    (OFF_K + 512*256)
#define OFF_V    (OFF_Q + 512*512)
#define OFF_MLP  (OFF_V + 512*256)
#define W_TOTAL  (OFF_MLP + 512*512)
__device__ __align__(16) __half g_wh[W_TOTAL];              // weights hi [n][k] concat
__device__ __align__(16) __half g_wl[W_TOTAL];              // weights lo

// ===========================================================================
// helpers
// ===========================================================================
__device__ __forceinline__ uint32_t smem_to_u32(const void* p) {
    uint32_t a;
    asm("{ .reg .u64 t; cvta.to.shared.u64 t, %1; cvt.u32.u64 %0, t; }"
        : "=r"(a) : "l"(p));
    return a;
}
__device__ __forceinline__ float warp_sum(float v) {
#pragma unroll
    for (int o = 16; o > 0; o >>= 1) v += __shfl_xor_sync(0xffffffffu, v, o);
    return v;
}
__device__ __forceinline__ void mma16816(float* c, const uint32_t* a, const uint32_t* b) {
    asm volatile("mma.sync.aligned.m16n8k16.row.col.f32.f16.f16.f32 "
        "{%0,%1,%2,%3}, {%4,%5,%6,%7}, {%8,%9}, {%0,%1,%2,%3};"
        : "+f"(c[0]), "+f"(c[1]), "+f"(c[2]), "+f"(c[3])
        : "r"(a[0]), "r"(a[1]), "r"(a[2]), "r"(a[3]), "r"(b[0]), "r"(b[1]));
}
__device__ __forceinline__ void ldsm4(uint32_t* r, uint32_t a) {
    asm volatile("ldmatrix.sync.aligned.m8n8.x4.shared.b16 {%0,%1,%2,%3}, [%4];"
        : "=r"(r[0]), "=r"(r[1]), "=r"(r[2]), "=r"(r[3]) : "r"(a));
}
__device__ __forceinline__ void ldsm4t(uint32_t* r, uint32_t a) {
    asm volatile("ldmatrix.sync.aligned.m8n8.x4.trans.shared.b16 {%0,%1,%2,%3}, [%4];"
        : "=r"(r[0]), "=r"(r[1]), "=r"(r[2]), "=r"(r[3]) : "r"(a));
}
__device__ __forceinline__ void cp16(uint32_t sm, const void* g) {
    asm volatile("cp.async.cg.shared.global [%0], [%1], 16;"
        :: "r"(sm), "l"(g) : "memory");
}
__device__ __forceinline__ void cp_commit() {
    asm volatile("cp.async.commit_group;" ::: "memory");
}
template<int N> __device__ __forceinline__ void cp_wait() {
    asm volatile("cp.async.wait_group %0;" :: "n"(N) : "memory");
}
__device__ __forceinline__ void split1f(float x, __half& h, __half& l) {
    h = __float2half_rn(x);
    l = __float2half_rn(x - __half2float(h));
}

// ===========================================================================
// split kernels
// ===========================================================================
__global__ __launch_bounds__(256)
void split_arr(const float* __restrict__ s, __half* __restrict__ h,
               __half* __restrict__ l, int n)
{
    int i = blockIdx.x * 256 + threadIdx.x;
    if (i < n) {
        __half hh, ll; split1f(s[i], hh, ll);
        h[i] = hh; l[i] = ll;
    }
}

__global__ __launch_bounds__(256)
void split_xin(const float* __restrict__ x)
{
    int i = blockIdx.x * 256 + threadIdx.x;      // < NB*CIN*HWP
    float v = x[i];
    __half h, l; split1f(v, h, l);
    g_ih[i] = h; g_il[i] = l;
    int p  = i & (HWP - 1);
    int bc = i >> 14;                 // HWP = 2^14
    int b  = bc >> 8, c = bc & 255;   // CIN = 256
    int hr = p >> 7, wc = p & 127;
    int kg = c * 4 + (hr & 1) * 2 + (wc & 1);
    int t  = (hr >> 1) * 64 + (wc >> 1);
    size_t o = ((size_t)b * 1024 + kg) * TT + t;
    g_ch[o] = h; g_cl[o] = l;
}

// ===========================================================================
// HMMA split-fp16 GEMM, fp16 hi/lo operands preloaded in global.
//   C[b][m][n] = sum_k A(m,k)*W[n][k] + bias[n]
//   KMAJOR=1: A[k][m] (k/v/conv)     KMAJOR=0: A[m][k] (q/mlp)
// Tile 128x128, K-chunk 32, 8 warps (2x4), warp tile 64x32, 3-stage cp.async.
// SMEM per stage (32KB):
//   A KMAJOR: 32 k-rows x 256B hi, +8192 lo; chunk^(k&7) swizzle
//   A MMAJOR / B: 128 rows x 128B = [4 hi | 4 lo] 16B-chunks, ^(row&7) swizzle
// ===========================================================================
#define STAGE   32768
#define SMEMDYN (3*STAGE)

template<int KMAJOR>
__global__ __launch_bounds__(256, 2)
void hgemm(const __half* __restrict__ Ah, const __half* __restrict__ Al,
           const __half* __restrict__ Bh, const __half* __restrict__ Bl,
           const float* __restrict__ bias, float* __restrict__ C,
           int M, int K)
{
    extern __shared__ char sm_[];
    const uint32_t sb = smem_to_u32(sm_);
    const int tid = threadIdx.x;
    const int lane = tid & 31;
    const int wid = tid >> 5;
    const int wm = wid & 1, wn = wid >> 1;
    const int m0 = blockIdx.x * 128, n0 = blockIdx.y * 128, bz = blockIdx.z;
    const __half* pAh = Ah + (size_t)bz * M * K;
    const __half* pAl = Al + (size_t)bz * M * K;

    float acc[4][4][4];
#pragma unroll
    for (int i = 0; i < 4; i++)
#pragma unroll
        for (int j = 0; j < 4; j++)
#pragma unroll
            for (int r = 0; r < 4; r++) acc[i][j][r] = 0.f;

    const int nch = K / 32;

    auto issue = [&](int s, int c) {
        const int k0 = c * 32;
        const uint32_t As = sb + s * STAGE;
        const uint32_t Bs = As + 16384;
        if (KMAJOR) {
#pragma unroll
            for (int j = 0; j < 2; j++) {
                int idx = tid + j * 256;
                int r = idx >> 4, ch = idx & 15;
                uint32_t so = r * 256 + ((ch ^ (r & 7)) << 4);
                size_t go = (size_t)(k0 + r) * M + m0 + ch * 8;
                cp16(As + so, pAh + go);
                cp16(As + 8192 + so, pAl + go);
            }
        } else {
#pragma unroll
            for (int j = 0; j < 4; j++) {
                int idx = tid + j * 256;
                int r = idx >> 3, q = idx & 7;
                uint32_t sm = As + r * 128 + ((q ^ (r & 7)) << 4);
                const __half* g = ((q < 4) ? pAh : pAl)
                                  + (size_t)(m0 + r) * K + k0 + (q & 3) * 8;
                cp16(sm, g);
            }
        }
#pragma unroll
        for (int j = 0; j < 4; j++) {
            int idx = tid + j * 256;
            int r = idx >> 3, q = idx & 7;
            uint32_t sm = Bs + r * 128 + ((q ^ (r & 7)) << 4);
            const __half* g = ((q < 4) ? Bh : Bl)
                              + (size_t)(n0 + r) * K + k0 + (q & 3) * 8;
            cp16(sm, g);
        }
        cp_commit();
    };

    auto computeCh = [&](int s) {
        const uint32_t As = sb + s * STAGE;
        const uint32_t Bs = As + 16384;
        const int g = lane >> 3;
        const uint32_t l7 = lane & 7;
#pragma unroll
        for (int ks = 0; ks < 2; ++ks) {
            uint32_t bh[8], bl[8];
            {
                uint32_t nrow = wn * 32 + (g >> 1) * 8 + l7;
                uint32_t cH = ((ks * 2 + (g & 1)) ^ l7) << 4;
                uint32_t cL = ((ks * 2 + (g & 1) + 4) ^ l7) << 4;
                uint32_t r0 = Bs + nrow * 128;
                ldsm4(&bh[0], r0 + cH);
                ldsm4(&bl[0], r0 + cL);
                uint32_t r1 = r0 + 16 * 128;
                ldsm4(&bh[4], r1 + cH);
                ldsm4(&bl[4], r1 + cL);
            }
#pragma unroll
            for (int mt = 0; mt < 4; ++mt) {
                uint32_t ah[4], al[4];
                if (KMAJOR) {
                    uint32_t krow = ks * 16 + (g >> 1) * 8 + l7;
                    uint32_t mch = wm * 8 + mt * 2 + (g & 1);
                    uint32_t a = As + krow * 256 + ((mch ^ l7) << 4);
                    ldsm4t(ah, a);
                    ldsm4t(al, a + 8192);
                } else {
                    uint32_t mrow = wm * 64 + mt * 16 + (g & 1) * 8 + l7;
                    uint32_t ch = ks * 2 + (g >> 1);
                    uint32_t ra = As + mrow * 128;
                    ldsm4(ah, ra + ((ch ^ l7) << 4));
                    ldsm4(al, ra + (((ch + 4) ^ l7) << 4));
                }
#pragma unroll
                for (int nt = 0; nt < 4; ++nt) {
                    mma16816(acc[mt][nt], ah, &bh[nt * 2]);
                    mma16816(acc[mt][nt], ah, &bl[nt * 2]);
                    mma16816(acc[mt][nt], al, &bh[nt * 2]);
                }
            }
        }
    };

    issue(0, 0);
    issue(1, 1);
    for (int c = 0; c < nch; ++c) {
        if (c + 2 < nch) cp_wait<1>(); else cp_wait<0>();
        __syncthreads();
        computeCh(c % 3);
        if (c + 2 < nch) issue((c + 2) % 3, c + 2);
        __syncthreads();
    }

    // ---- epilogue ----
    const int gq = lane >> 2, tq = lane & 3;
#pragma unroll
    for (int mt = 0; mt < 4; ++mt) {
        int mrow = m0 + wm * 64 + mt * 16 + gq;
        float* Cr = C + ((size_t)bz * M + mrow) * CO + n0;
#pragma unroll
        for (int nt = 0; nt < 4; ++nt) {
            int col = wn * 32 + nt * 8 + tq * 2;
            float b0 = bias[n0 + col], b1 = bias[n0 + col + 1];
            float2 v0; v0.x = acc[mt][nt][0] + b0; v0.y = acc[mt][nt][1] + b1;
            *(float2*)&Cr[col] = v0;
            float2 v1; v1.x = acc[mt][nt][2] + b0; v1.y = acc[mt][nt][3] + b1;
            *(float2*)&Cr[col + 8 * CO] = v1;
        }
    }
}

// ---------------------------------------------------------------------------
// Channel LayerNorm over CO=512; also emits fp16 hi/lo of the result row.
// ---------------------------------------------------------------------------
__global__ __launch_bounds__(256)
void ln_kernel(const float* __restrict__ in, float* __restrict__ xo,
               __half* __restrict__ xh, __half* __restrict__ xl,
               const float* __restrict__ g, const float* __restrict__ bvec, int add)
{
    const int tid = threadIdx.x;
    const size_t row = blockIdx.x;
    const float* r = in + row * CO;
    float v0 = r[tid], v1 = r[tid + 256];
    float s  = v0 + v1;
    float s2 = v0 * v0 + v1 * v1;
    s  = warp_sum(s);
    s2 = warp_sum(s2);
    __shared__ float r1[8], r2[8];
    const int lane = tid & 31, warp = tid >> 5;
    if (lane == 0) { r1[warp] = s; r2[warp] = s2; }
    __syncthreads();
    float ss = 0.f, sq = 0.f;
#pragma unroll
    for (int i = 0; i < 8; i++) { ss += r1[i]; sq += r2[i]; }
    float mu  = ss / CO;
    float var = sq / CO - mu * mu;
    float rs  = rsqrtf(var + EPSF);
    float o0 = (v0 - mu) * rs * g[tid]       + bvec[tid];
    float o1 = (v1 - mu) * rs * g[tid + 256] + bvec[tid + 256];
    float* xr = xo + row * CO;
    float f0, f1;
    if (add) { f0 = xr[tid] + o0; f1 = xr[tid + 256] + o1; }
    else     { f0 = o0;           f1 = o1; }
    xr[tid] = f0; xr[tid + 256] = f1;
    __half h, l;
    split1f(f0, h, l); xh[row * CO + tid] = h;       xl[row * CO + tid] = l;
    split1f(f1, h, l); xh[row * CO + tid + 256] = h; xl[row * CO + tid + 256] = l;
}

// ---------------------------------------------------------------------------
// Fused attention step; also emits fp16 hi/lo of the updated x row.
// ---------------------------------------------------------------------------
__global__ __launch_bounds__(256)
void att_kernel(const float* __restrict__ qb, const float* __restrict__ kb,
                const float* __restrict__ vb, float* __restrict__ xb,
                __half* __restrict__ xh, __half* __restrict__ xl,
                const float* __restrict__ lg, const float* __restrict__ lb)
{
    const int tid = threadIdx.x;
    const int row = blockIdx.x;            // b*T + t
    const int b = row >> 12;
    const int t = row & (TT - 1);
    const int ho = t >> 6, wo = t & 63;
    const int pix0 = (ho << 1) * WW + (wo << 1);
    const size_t base = ((size_t)b * HWP + pix0) * CO;
    const float* kp = kb + base;
    const float* vp = vb + base;
    const float* qr = qb + (size_t)row * CO;

    const size_t S1 = CO;
    const size_t S2 = (size_t)WW * CO;
    const size_t S3 = S2 + CO;

    float q0 = qr[tid], q1 = qr[tid + 256];
    float d0 = q0 * kp[tid]      + q1 * kp[tid + 256];
    float d1 = q0 * kp[S1 + tid] + q1 * kp[S1 + tid + 256];
    float d2 = q0 * kp[S2 + tid] + q1 * kp[S2 + tid + 256];
    float d3 = q0 * kp[S3 + tid] + q1 * kp[S3 + tid + 256];
    d0 = warp_sum(d0); d1 = warp_sum(d1); d2 = warp_sum(d2); d3 = warp_sum(d3);

    __shared__ float red[4][8];
    __shared__ float r1[8], r2[8];
    const int lane = tid & 31, warp = tid >> 5;
    if (lane == 0) { red[0][warp] = d0; red[1][warp] = d1;
                     red[2][warp] = d2; red[3][warp] = d3; }
    __syncthreads();
    float a0 = 0.f, a1 = 0.f, a2 = 0.f, a3 = 0.f;
#pragma unroll
    for (int i = 0; i < 8; i++) {
        a0 += red[0][i]; a1 += red[1][i]; a2 += red[2][i]; a3 += red[3][i];
    }
    float mx = fmaxf(fmaxf(a0, a1), fmaxf(a2, a3));
    float e0 = __expf(a0 - mx), e1 = __expf(a1 - mx);
    float e2 = __expf(a2 - mx), e3 = __expf(a3 - mx);
    float inv = 1.f / (e0 + e1 + e2 + e3);
    e0 *= inv; e1 *= inv; e2 *= inv; e3 *= inv;

    float u0 = e0 * vp[tid]       + e1 * vp[S1 + tid]
             + e2 * vp[S2 + tid]  + e3 * vp[S3 + tid];
    float u1 = e0 * vp[tid + 256]      + e1 * vp[S1 + tid + 256]
             + e2 * vp[S2 + tid + 256] + e3 * vp[S3 + tid + 256];

    float s  = u0 + u1;
    float s2 = u0 * u0 + u1 * u1;
    s  = warp_sum(s);
    s2 = warp_sum(s2);
    if (lane == 0) { r1[warp] = s; r2[warp] = s2; }
    __syncthreads();
    float ss = 0.f, sq = 0.f;
#pragma unroll
    for (int i = 0; i < 8; i++) { ss += r1[i]; sq += r2[i]; }
    float mu  = ss / CO;
    float var = sq / CO - mu * mu;
    float rs  = rsqrtf(var + EPSF);

    float* xo = xb + (size_t)row * CO;
    float f0 = xo[tid]       + (u0 - mu) * rs * lg[tid]       + lb[tid];
    float f1 = xo[tid + 256] + (u1 - mu) * rs * lg[tid + 256] + lb[tid + 256];
    xo[tid] = f0; xo[tid + 256] = f1;
    __half h, l;
    split1f(f0, h, l); xh[(size_t)row * CO + tid] = h;       xl[(size_t)row * CO + tid] = l;
    split1f(f1, h, l); xh[(size_t)row * CO + tid + 256] = h; xl[(size_t)row * CO + tid + 256] = l;
}

// ---------------------------------------------------------------------------
// Final transpose (B,T,CO) pixel-major -> NCHW output (B,CO,64,64)
// ---------------------------------------------------------------------------
__global__ void transpose_kernel(const float* __restrict__ x, float* __restrict__ out)
{
    __shared__ float tile[32][33];
    const int b  = blockIdx.z;
    const int t0 = blockIdx.x * 32;
    const int f0 = blockIdx.y * 32;
    const int tx = threadIdx.x, ty = threadIdx.y;
#pragma unroll
    for (int j = 0; j < 32; j += 8)
        tile[ty + j][tx] = x[((size_t)b * TT + t0 + ty + j) * CO + f0 + tx];
    __syncthreads();
#pragma unroll
    for (int j = 0; j < 32; j += 8)
        out[((size_t)b * CO + f0 + ty + j) * TT + t0 + tx] = tile[tx][ty + j];
}

// ---------------------------------------------------------------------------
extern "C" void kernel_launch(void* const* d_in, const int* in_sizes, int n_in,
                              void* d_out, int out_size)
{
    const float* x_in   = (const float*)d_in[0];
    const float* conv_w = (const float*)d_in[1];
    const float* conv_b = (const float*)d_in[2];
    const float* k_w    = (const float*)d_in[3];
    const float* k_b    = (const float*)d_in[4];
    const float* q_w    = (const float*)d_in[5];
    const float* q_b    = (const float*)d_in[6];
    const float* v_w    = (const float*)d_in[7];
    const float* v_b    = (const float*)d_in[8];
    const float* mlp_w  = (const float*)d_in[9];
    const float* mlp_b  = (const float*)d_in[10];
    const float* lnc_g  = (const float*)d_in[11];
    const float* lnc_b  = (const float*)d_in[12];
    const float* lnv_g  = (const float*)d_in[13];
    const float* lnv_b  = (const float*)d_in[14];
    const float* lnm_g  = (const float*)d_in[15];
    const float* lnm_b  = (const float*)d_in[16];
    float* out = (float*)d_out;

    float *pk, *pv, *px, *pq;
    __half *ih, *il, *ch, *cl, *xh, *xl, *wh, *wl;
    cudaGetSymbolAddress((void**)&pk, g_k);
    cudaGetSymbolAddress((void**)&pv, g_v);
    cudaGetSymbolAddress((void**)&px, g_x);
    cudaGetSymbolAddress((void**)&pq, g_q);
    cudaGetSymbolAddress((void**)&ih, g_ih);
    cudaGetSymbolAddress((void**)&il, g_il);
    cudaGetSymbolAddress((void**)&ch, g_ch);
    cudaGetSymbolAddress((void**)&cl, g_cl);
    cudaGetSymbolAddress((void**)&xh, g_xh);
    cudaGetSymbolAddress((void**)&xl, g_xl);
    cudaGetSymbolAddress((void**)&wh, g_wh);
    cudaGetSymbolAddress((void**)&wl, g_wl);

    cudaFuncSetAttribute(hgemm<0>, cudaFuncAttributeMaxDynamicSharedMemorySize, SMEMDYN);
    cudaFuncSetAttribute(hgemm<1>, cudaFuncAttributeMaxDynamicSharedMemorySize, SMEMDYN);

    // 0) split weights + input
    split_arr<<<512 * 1024 / 256, 256>>>(conv_w, wh + OFF_CONV, wl + OFF_CONV, 512 * 1024);
    split_arr<<<512 * 256 / 256, 256>>>(k_w,   wh + OFF_K,   wl + OFF_K,   512 * 256);
    split_arr<<<512 * 512 / 256, 256>>>(q_w,   wh + OFF_Q,   wl + OFF_Q,   512 * 512);
    split_arr<<<512 * 256 / 256, 256>>>(v_w,   wh + OFF_V,   wl + OFF_V,   512 * 256);
    split_arr<<<512 * 512 / 256, 256>>>(mlp_w, wh + OFF_MLP, wl + OFF_MLP, 512 * 512);
    split_xin<<<NB * CIN * HWP / 256, 256>>>(x_in);

    const dim3 gq(TT / 128, CO / 128, NB);     // conv/q/mlp GEMMs
    const dim3 gkv(HWP / 128, CO / 128, NB);   // k/v GEMMs

    // 1) patchify conv (K-major im2col) -> staging, then channel LN -> x_out
    hgemm<1><<<gq, 256, SMEMDYN>>>(ch, cl, wh + OFF_CONV, wl + OFF_CONV, conv_b, pq, TT, 1024);
    ln_kernel<<<NB * TT, 256>>>(pq, px, xh, xl, lnc_g, lnc_b, 0);

    // 2) k, v projections at full resolution (K-major)
    hgemm<1><<<gkv, 256, SMEMDYN>>>(ih, il, wh + OFF_K, wl + OFF_K, k_b, pk, HWP, CIN);
    hgemm<1><<<gkv, 256, SMEMDYN>>>(ih, il, wh + OFF_V, wl + OFF_V, v_b, pv, HWP, CIN);

    // 3) iterative grouping
    for (int it = 0; it < ITERS; it++) {
        hgemm<0><<<gq, 256, SMEMDYN>>>(xh, xl, wh + OFF_Q, wl + OFF_Q, q_b, pq, TT, CO);
        att_kernel<<<NB * TT, 256>>>(pq, pk, pv, px, xh, xl, lnv_g, lnv_b);
        hgemm<0><<<gq, 256, SMEMDYN>>>(xh, xl, wh + OFF_MLP, wl + OFF_MLP, mlp_b, pq, TT, CO);
        ln_kernel<<<NB * TT, 256>>>(pq, px, xh, xl, lnm_g, lnm_b, 1);
    }

    // 4) pixel-major -> NCHW output
    transpose_kernel<<<dim3(TT / 32, CO / 32, NB), dim3(32, 8)>>>(px, out);
}

// round 5
// speedup vs baseline: 2.4149x; 1.0675x over previous
#include <cuda_runtime.h>
#include <cuda_fp16.h>
#include <cstdint>

// Problem constants
#define NB   4
#define CIN  256
#define HH   128
#define WW   128
#define HWP  (HH*WW)      // 16384
#define CO   512
#define TT   4096         // 64*64 output pixels
#define EPSF 1e-5f
#define ITERS 3

// ---------------------------------------------------------------------------
// Scratch
// ---------------------------------------------------------------------------
__device__ float g_k[(size_t)NB*HWP*CO];   // 128 MB  k projection, (B,HW,CO) fp32
__device__ float g_v[(size_t)NB*HWP*CO];   // 128 MB  v projection
__device__ float g_x[(size_t)NB*TT*CO];    //  32 MB  x_out, (B,T,CO) fp32
__device__ float g_q[(size_t)NB*TT*CO];    //  32 MB  q / mlp / conv staging

// fp16 split operands
__device__ __align__(16) __half g_ih[(size_t)NB*CIN*HWP];   // x_in hi, K-major [b][c][pix]
__device__ __align__(16) __half g_il[(size_t)NB*CIN*HWP];   // x_in lo
__device__ __align__(16) __half g_ch[(size_t)NB*1024*TT];   // im2col x_in hi [b][c*4+w][t]
__device__ __align__(16) __half g_cl[(size_t)NB*1024*TT];   // im2col lo
__device__ __align__(16) __half g_xh[(size_t)NB*TT*CO];     // x_out hi, M-major [b][t][c]
__device__ __align__(16) __half g_xl[(size_t)NB*TT*CO];     // x_out lo
#define OFF_CONV 0
#define OFF_K    (512*1024)
#define OFF_Q    (OFF_K + 512*256)
#define OFF_V    (OFF_Q + 512*512)
#define OFF_MLP  (OFF_V + 512*256)
#define W_TOTAL  (OFF_MLP + 512*512)
__device__ __align__(16) __half g_wh[W_TOTAL];              // weights hi [n][k] concat
__device__ __align__(16) __half g_wl[W_TOTAL];              // weights lo

// ===========================================================================
// helpers
// ===========================================================================
__device__ __forceinline__ uint32_t smem_to_u32(const void* p) {
    uint32_t a;
    asm("{ .reg .u64 t; cvta.to.shared.u64 t, %1; cvt.u32.u64 %0, t; }"
        : "=r"(a) : "l"(p));
    return a;
}
__device__ __forceinline__ float warp_sum(float v) {
#pragma unroll
    for (int o = 16; o > 0; o >>= 1) v += __shfl_xor_sync(0xffffffffu, v, o);
    return v;
}
__device__ __forceinline__ void mma16816(float* c, const uint32_t* a, const uint32_t* b) {
    asm volatile("mma.sync.aligned.m16n8k16.row.col.f32.f16.f16.f32 "
        "{%0,%1,%2,%3}, {%4,%5,%6,%7}, {%8,%9}, {%0,%1,%2,%3};"
        : "+f"(c[0]), "+f"(c[1]), "+f"(c[2]), "+f"(c[3])
        : "r"(a[0]), "r"(a[1]), "r"(a[2]), "r"(a[3]), "r"(b[0]), "r"(b[1]));
}
__device__ __forceinline__ void ldsm4(uint32_t* r, uint32_t a) {
    asm volatile("ldmatrix.sync.aligned.m8n8.x4.shared.b16 {%0,%1,%2,%3}, [%4];"
        : "=r"(r[0]), "=r"(r[1]), "=r"(r[2]), "=r"(r[3]) : "r"(a));
}
__device__ __forceinline__ void ldsm4t(uint32_t* r, uint32_t a) {
    asm volatile("ldmatrix.sync.aligned.m8n8.x4.trans.shared.b16 {%0,%1,%2,%3}, [%4];"
        : "=r"(r[0]), "=r"(r[1]), "=r"(r[2]), "=r"(r[3]) : "r"(a));
}
__device__ __forceinline__ void cp16(uint32_t sm, const void* g) {
    asm volatile("cp.async.cg.shared.global [%0], [%1], 16;"
        :: "r"(sm), "l"(g) : "memory");
}
__device__ __forceinline__ void cp_commit() {
    asm volatile("cp.async.commit_group;" ::: "memory");
}
template<int N> __device__ __forceinline__ void cp_wait() {
    asm volatile("cp.async.wait_group %0;" :: "n"(N) : "memory");
}
__device__ __forceinline__ void split1f(float x, __half& h, __half& l) {
    h = __float2half_rn(x);
    l = __float2half_rn(x - __half2float(h));
}

// ===========================================================================
// split kernels
// ===========================================================================
__global__ __launch_bounds__(256)
void split_arr(const float* __restrict__ s, __half* __restrict__ h,
               __half* __restrict__ l, int n)
{
    int i = blockIdx.x * 256 + threadIdx.x;
    if (i < n) {
        __half hh, ll; split1f(s[i], hh, ll);
        h[i] = hh; l[i] = ll;
    }
}

__global__ __launch_bounds__(256)
void split_xin(const float* __restrict__ x)
{
    int i = blockIdx.x * 256 + threadIdx.x;      // < NB*CIN*HWP
    float v = x[i];
    __half h, l; split1f(v, h, l);
    g_ih[i] = h; g_il[i] = l;
    int p  = i & (HWP - 1);
    int bc = i >> 14;                 // HWP = 2^14
    int b  = bc >> 8, c = bc & 255;   // CIN = 256
    int hr = p >> 7, wc = p & 127;
    int kg = c * 4 + (hr & 1) * 2 + (wc & 1);
    int t  = (hr >> 1) * 64 + (wc >> 1);
    size_t o = ((size_t)b * 1024 + kg) * TT + t;
    g_ch[o] = h; g_cl[o] = l;
}

// ===========================================================================
// HMMA split-fp16 GEMM, fp16 hi/lo operands preloaded in global.
//   C[b][m][n] = sum_k A(m,k)*W[n][k] + bias[n]
//   KMAJOR=1: A[k][m] (k/v/conv)     KMAJOR=0: A[m][k] (q/mlp)
// Tile 128x128, K-chunk 32, 8 warps (2x4), warp tile 64x32, 3-stage cp.async,
// single barrier per chunk, term-major MMA order (no same-acc RAW chains).
// ===========================================================================
#define STAGE   32768
#define SMEMDYN (3*STAGE)

template<int KMAJOR, int NCH>
__global__ __launch_bounds__(256, 2)
void hgemm(const __half* __restrict__ Ah, const __half* __restrict__ Al,
           const __half* __restrict__ Bh, const __half* __restrict__ Bl,
           const float* __restrict__ bias, float* __restrict__ C,
           int M)
{
    constexpr int K = NCH * 32;
    extern __shared__ char sm_[];
    const uint32_t sb = smem_to_u32(sm_);
    const int tid = threadIdx.x;
    const int lane = tid & 31;
    const int wid = tid >> 5;
    const int wm = wid & 1, wn = wid >> 1;
    const int m0 = blockIdx.x * 128, n0 = blockIdx.y * 128, bz = blockIdx.z;
    const __half* pAh = Ah + (size_t)bz * M * K;
    const __half* pAl = Al + (size_t)bz * M * K;

    float acc[4][4][4];
#pragma unroll
    for (int i = 0; i < 4; i++)
#pragma unroll
        for (int j = 0; j < 4; j++)
#pragma unroll
            for (int r = 0; r < 4; r++) acc[i][j][r] = 0.f;

    auto issue = [&](int s, int c) {
        const int k0 = c * 32;
        const uint32_t As = sb + s * STAGE;
        const uint32_t Bs = As + 16384;
        if (KMAJOR) {
#pragma unroll
            for (int j = 0; j < 2; j++) {
                int idx = tid + j * 256;
                int r = idx >> 4, ch = idx & 15;
                uint32_t so = r * 256 + ((ch ^ (r & 7)) << 4);
                size_t go = (size_t)(k0 + r) * M + m0 + ch * 8;
                cp16(As + so, pAh + go);
                cp16(As + 8192 + so, pAl + go);
            }
        } else {
#pragma unroll
            for (int j = 0; j < 4; j++) {
                int idx = tid + j * 256;
                int r = idx >> 3, q = idx & 7;
                uint32_t sm = As + r * 128 + ((q ^ (r & 7)) << 4);
                const __half* g = ((q < 4) ? pAh : pAl)
                                  + (size_t)(m0 + r) * K + k0 + (q & 3) * 8;
                cp16(sm, g);
            }
        }
#pragma unroll
        for (int j = 0; j < 4; j++) {
            int idx = tid + j * 256;
            int r = idx >> 3, q = idx & 7;
            uint32_t sm = Bs + r * 128 + ((q ^ (r & 7)) << 4);
            const __half* g = ((q < 4) ? Bh : Bl)
                              + (size_t)(n0 + r) * K + k0 + (q & 3) * 8;
            cp16(sm, g);
        }
        cp_commit();
    };

    auto computeCh = [&](int s) {
        const uint32_t As = sb + s * STAGE;
        const uint32_t Bs = As + 16384;
        const int g = lane >> 3;
        const uint32_t l7 = lane & 7;
#pragma unroll
        for (int ks = 0; ks < 2; ++ks) {
            uint32_t bh[8], bl[8];
            {
                uint32_t nrow = wn * 32 + (g >> 1) * 8 + l7;
                uint32_t cH = ((ks * 2 + (g & 1)) ^ l7) << 4;
                uint32_t cL = ((ks * 2 + (g & 1) + 4) ^ l7) << 4;
                uint32_t r0 = Bs + nrow * 128;
                ldsm4(&bh[0], r0 + cH);
                ldsm4(&bl[0], r0 + cL);
                uint32_t r1 = r0 + 16 * 128;
                ldsm4(&bh[4], r1 + cH);
                ldsm4(&bl[4], r1 + cL);
            }
#pragma unroll
            for (int mt = 0; mt < 4; ++mt) {
                uint32_t ah[4], al[4];
                if (KMAJOR) {
                    uint32_t krow = ks * 16 + (g >> 1) * 8 + l7;
                    uint32_t mch = wm * 8 + mt * 2 + (g & 1);
                    uint32_t a = As + krow * 256 + ((mch ^ l7) << 4);
                    ldsm4t(ah, a);
                    ldsm4t(al, a + 8192);
                } else {
                    uint32_t mrow = wm * 64 + mt * 16 + (g & 1) * 8 + l7;
                    uint32_t ch = ks * 2 + (g >> 1);
                    uint32_t ra = As + mrow * 128;
                    ldsm4(ah, ra + ((ch ^ l7) << 4));
                    ldsm4(al, ra + (((ch + 4) ^ l7) << 4));
                }
                // term-major: 4 independent MMAs between same-acc reuses,
                // per-acc order stays hh -> hl -> lh (bit-identical results)
#pragma unroll
                for (int nt = 0; nt < 4; ++nt) mma16816(acc[mt][nt], ah, &bh[nt * 2]);
#pragma unroll
                for (int nt = 0; nt < 4; ++nt) mma16816(acc[mt][nt], ah, &bl[nt * 2]);
#pragma unroll
                for (int nt = 0; nt < 4; ++nt) mma16816(acc[mt][nt], al, &bh[nt * 2]);
            }
        }
    };

    issue(0, 0);
    issue(1, 1);
#pragma unroll
    for (int c = 0; c < NCH; ++c) {
        if (c < NCH - 1) cp_wait<1>(); else cp_wait<0>();
        __syncthreads();
        if (c + 2 < NCH) issue((c + 2) % 3, c + 2);
        computeCh(c % 3);
    }

    // ---- epilogue ----
    const int gq = lane >> 2, tq = lane & 3;
#pragma unroll
    for (int mt = 0; mt < 4; ++mt) {
        int mrow = m0 + wm * 64 + mt * 16 + gq;
        float* Cr = C + ((size_t)bz * M + mrow) * CO + n0;
#pragma unroll
        for (int nt = 0; nt < 4; ++nt) {
            int col = wn * 32 + nt * 8 + tq * 2;
            float b0 = bias[n0 + col], b1 = bias[n0 + col + 1];
            float2 v0; v0.x = acc[mt][nt][0] + b0; v0.y = acc[mt][nt][1] + b1;
            *(float2*)&Cr[col] = v0;
            float2 v1; v1.x = acc[mt][nt][2] + b0; v1.y = acc[mt][nt][3] + b1;
            *(float2*)&Cr[col + 8 * CO] = v1;
        }
    }
}

// ---------------------------------------------------------------------------
// Channel LayerNorm over CO=512; also emits fp16 hi/lo of the result row.
// ---------------------------------------------------------------------------
__global__ __launch_bounds__(256)
void ln_kernel(const float* __restrict__ in, float* __restrict__ xo,
               __half* __restrict__ xh, __half* __restrict__ xl,
               const float* __restrict__ g, const float* __restrict__ bvec, int add)
{
    const int tid = threadIdx.x;
    const size_t row = blockIdx.x;
    const float* r = in + row * CO;
    float v0 = r[tid], v1 = r[tid + 256];
    float s  = v0 + v1;
    float s2 = v0 * v0 + v1 * v1;
    s  = warp_sum(s);
    s2 = warp_sum(s2);
    __shared__ float r1[8], r2[8];
    const int lane = tid & 31, warp = tid >> 5;
    if (lane == 0) { r1[warp] = s; r2[warp] = s2; }
    __syncthreads();
    float ss = 0.f, sq = 0.f;
#pragma unroll
    for (int i = 0; i < 8; i++) { ss += r1[i]; sq += r2[i]; }
    float mu  = ss / CO;
    float var = sq / CO - mu * mu;
    float rs  = rsqrtf(var + EPSF);
    float o0 = (v0 - mu) * rs * g[tid]       + bvec[tid];
    float o1 = (v1 - mu) * rs * g[tid + 256] + bvec[tid + 256];
    float* xr = xo + row * CO;
    float f0, f1;
    if (add) { f0 = xr[tid] + o0; f1 = xr[tid + 256] + o1; }
    else     { f0 = o0;           f1 = o1; }
    xr[tid] = f0; xr[tid + 256] = f1;
    __half h, l;
    split1f(f0, h, l); xh[row * CO + tid] = h;       xl[row * CO + tid] = l;
    split1f(f1, h, l); xh[row * CO + tid + 256] = h; xl[row * CO + tid + 256] = l;
}

// ---------------------------------------------------------------------------
// Fused attention step; also emits fp16 hi/lo of the updated x row.
// ---------------------------------------------------------------------------
__global__ __launch_bounds__(256)
void att_kernel(const float* __restrict__ qb, const float* __restrict__ kb,
                const float* __restrict__ vb, float* __restrict__ xb,
                __half* __restrict__ xh, __half* __restrict__ xl,
                const float* __restrict__ lg, const float* __restrict__ lb)
{
    const int tid = threadIdx.x;
    const int row = blockIdx.x;            // b*T + t
    const int b = row >> 12;
    const int t = row & (TT - 1);
    const int ho = t >> 6, wo = t & 63;
    const int pix0 = (ho << 1) * WW + (wo << 1);
    const size_t base = ((size_t)b * HWP + pix0) * CO;
    const float* kp = kb + base;
    const float* vp = vb + base;
    const float* qr = qb + (size_t)row * CO;

    const size_t S1 = CO;
    const size_t S2 = (size_t)WW * CO;
    const size_t S3 = S2 + CO;

    float q0 = qr[tid], q1 = qr[tid + 256];
    float d0 = q0 * kp[tid]      + q1 * kp[tid + 256];
    float d1 = q0 * kp[S1 + tid] + q1 * kp[S1 + tid + 256];
    float d2 = q0 * kp[S2 + tid] + q1 * kp[S2 + tid + 256];
    float d3 = q0 * kp[S3 + tid] + q1 * kp[S3 + tid + 256];
    d0 = warp_sum(d0); d1 = warp_sum(d1); d2 = warp_sum(d2); d3 = warp_sum(d3);

    __shared__ float red[4][8];
    __shared__ float r1[8], r2[8];
    const int lane = tid & 31, warp = tid >> 5;
    if (lane == 0) { red[0][warp] = d0; red[1][warp] = d1;
                     red[2][warp] = d2; red[3][warp] = d3; }
    __syncthreads();
    float a0 = 0.f, a1 = 0.f, a2 = 0.f, a3 = 0.f;
#pragma unroll
    for (int i = 0; i < 8; i++) {
        a0 += red[0][i]; a1 += red[1][i]; a2 += red[2][i]; a3 += red[3][i];
    }
    float mx = fmaxf(fmaxf(a0, a1), fmaxf(a2, a3));
    float e0 = __expf(a0 - mx), e1 = __expf(a1 - mx);
    float e2 = __expf(a2 - mx), e3 = __expf(a3 - mx);
    float inv = 1.f / (e0 + e1 + e2 + e3);
    e0 *= inv; e1 *= inv; e2 *= inv; e3 *= inv;

    float u0 = e0 * vp[tid]       + e1 * vp[S1 + tid]
             + e2 * vp[S2 + tid]  + e3 * vp[S3 + tid];
    float u1 = e0 * vp[tid + 256]      + e1 * vp[S1 + tid + 256]
             + e2 * vp[S2 + tid + 256] + e3 * vp[S3 + tid + 256];

    float s  = u0 + u1;
    float s2 = u0 * u0 + u1 * u1;
    s  = warp_sum(s);
    s2 = warp_sum(s2);
    if (lane == 0) { r1[warp] = s; r2[warp] = s2; }
    __syncthreads();
    float ss = 0.f, sq = 0.f;
#pragma unroll
    for (int i = 0; i < 8; i++) { ss += r1[i]; sq += r2[i]; }
    float mu  = ss / CO;
    float var = sq / CO - mu * mu;
    float rs  = rsqrtf(var + EPSF);

    float* xo = xb + (size_t)row * CO;
    float f0 = xo[tid]       + (u0 - mu) * rs * lg[tid]       + lb[tid];
    float f1 = xo[tid + 256] + (u1 - mu) * rs * lg[tid + 256] + lb[tid + 256];
    xo[tid] = f0; xo[tid + 256] = f1;
    __half h, l;
    split1f(f0, h, l); xh[(size_t)row * CO + tid] = h;       xl[(size_t)row * CO + tid] = l;
    split1f(f1, h, l); xh[(size_t)row * CO + tid + 256] = h; xl[(size_t)row * CO + tid + 256] = l;
}

// ---------------------------------------------------------------------------
// Final transpose (B,T,CO) pixel-major -> NCHW output (B,CO,64,64)
// ---------------------------------------------------------------------------
__global__ void transpose_kernel(const float* __restrict__ x, float* __restrict__ out)
{
    __shared__ float tile[32][33];
    const int b  = blockIdx.z;
    const int t0 = blockIdx.x * 32;
    const int f0 = blockIdx.y * 32;
    const int tx = threadIdx.x, ty = threadIdx.y;
#pragma unroll
    for (int j = 0; j < 32; j += 8)
        tile[ty + j][tx] = x[((size_t)b * TT + t0 + ty + j) * CO + f0 + tx];
    __syncthreads();
#pragma unroll
    for (int j = 0; j < 32; j += 8)
        out[((size_t)b * CO + f0 + ty + j) * TT + t0 + tx] = tile[tx][ty + j];
}

// ---------------------------------------------------------------------------
extern "C" void kernel_launch(void* const* d_in, const int* in_sizes, int n_in,
                              void* d_out, int out_size)
{
    const float* x_in   = (const float*)d_in[0];
    const float* conv_w = (const float*)d_in[1];
    const float* conv_b = (const float*)d_in[2];
    const float* k_w    = (const float*)d_in[3];
    const float* k_b    = (const float*)d_in[4];
    const float* q_w    = (const float*)d_in[5];
    const float* q_b    = (const float*)d_in[6];
    const float* v_w    = (const float*)d_in[7];
    const float* v_b    = (const float*)d_in[8];
    const float* mlp_w  = (const float*)d_in[9];
    const float* mlp_b  = (const float*)d_in[10];
    const float* lnc_g  = (const float*)d_in[11];
    const float* lnc_b  = (const float*)d_in[12];
    const float* lnv_g  = (const float*)d_in[13];
    const float* lnv_b  = (const float*)d_in[14];
    const float* lnm_g  = (const float*)d_in[15];
    const float* lnm_b  = (const float*)d_in[16];
    float* out = (float*)d_out;

    float *pk, *pv, *px, *pq;
    __half *ih, *il, *ch, *cl, *xh, *xl, *wh, *wl;
    cudaGetSymbolAddress((void**)&pk, g_k);
    cudaGetSymbolAddress((void**)&pv, g_v);
    cudaGetSymbolAddress((void**)&px, g_x);
    cudaGetSymbolAddress((void**)&pq, g_q);
    cudaGetSymbolAddress((void**)&ih, g_ih);
    cudaGetSymbolAddress((void**)&il, g_il);
    cudaGetSymbolAddress((void**)&ch, g_ch);
    cudaGetSymbolAddress((void**)&cl, g_cl);
    cudaGetSymbolAddress((void**)&xh, g_xh);
    cudaGetSymbolAddress((void**)&xl, g_xl);
    cudaGetSymbolAddress((void**)&wh, g_wh);
    cudaGetSymbolAddress((void**)&wl, g_wl);

    cudaFuncSetAttribute(hgemm<1,32>, cudaFuncAttributeMaxDynamicSharedMemorySize, SMEMDYN);
    cudaFuncSetAttribute(hgemm<1,8>,  cudaFuncAttributeMaxDynamicSharedMemorySize, SMEMDYN);
    cudaFuncSetAttribute(hgemm<0,16>, cudaFuncAttributeMaxDynamicSharedMemorySize, SMEMDYN);

    // 0) split weights + input
    split_arr<<<512 * 1024 / 256, 256>>>(conv_w, wh + OFF_CONV, wl + OFF_CONV, 512 * 1024);
    split_arr<<<512 * 256 / 256, 256>>>(k_w,   wh + OFF_K,   wl + OFF_K,   512 * 256);
    split_arr<<<512 * 512 / 256, 256>>>(q_w,   wh + OFF_Q,   wl + OFF_Q,   512 * 512);
    split_arr<<<512 * 256 / 256, 256>>>(v_w,   wh + OFF_V,   wl + OFF_V,   512 * 256);
    split_arr<<<512 * 512 / 256, 256>>>(mlp_w, wh + OFF_MLP, wl + OFF_MLP, 512 * 512);
    split_xin<<<NB * CIN * HWP / 256, 256>>>(x_in);

    const dim3 gq(TT / 128, CO / 128, NB);     // conv/q/mlp GEMMs
    const dim3 gkv(HWP / 128, CO / 128, NB);   // k/v GEMMs

    // 1) patchify conv (K-major im2col) -> staging, then channel LN -> x_out
    hgemm<1,32><<<gq, 256, SMEMDYN>>>(ch, cl, wh + OFF_CONV, wl + OFF_CONV, conv_b, pq, TT);
    ln_kernel<<<NB * TT, 256>>>(pq, px, xh, xl, lnc_g, lnc_b, 0);

    // 2) k, v projections at full resolution (K-major)
    hgemm<1,8><<<gkv, 256, SMEMDYN>>>(ih, il, wh + OFF_K, wl + OFF_K, k_b, pk, HWP);
    hgemm<1,8><<<gkv, 256, SMEMDYN>>>(ih, il, wh + OFF_V, wl + OFF_V, v_b, pv, HWP);

    // 3) iterative grouping
    for (int it = 0; it < ITERS; it++) {
        hgemm<0,16><<<gq, 256, SMEMDYN>>>(xh, xl, wh + OFF_Q, wl + OFF_Q, q_b, pq, TT);
        att_kernel<<<NB * TT, 256>>>(pq, pk, pv, px, xh, xl, lnv_g, lnv_b);
        hgemm<0,16><<<gq, 256, SMEMDYN>>>(xh, xl, wh + OFF_MLP, wl + OFF_MLP, mlp_b, pq, TT);
        ln_kernel<<<NB * TT, 256>>>(pq, px, xh, xl, lnm_g, lnm_b, 1);
    }

    // 4) pixel-major -> NCHW output
    transpose_kernel<<<dim3(TT / 32, CO / 32, NB), dim3(32, 8)>>>(px, out);
}

// round 6
// speedup vs baseline: 2.4405x; 1.0106x over previous
#include <cuda_runtime.h>
#include <cuda_fp16.h>
#include <cstdint>

// Problem constants
#define NB   4
#define CIN  256
#define HH   128
#define WW   128
#define HWP  (HH*WW)      // 16384
#define CO   512
#define TT   4096         // 64*64 output pixels
#define EPSF 1e-5f
#define ITERS 3

// ---------------------------------------------------------------------------
// Scratch
// ---------------------------------------------------------------------------
__device__ float g_k[(size_t)NB*HWP*CO];   // k projection, (B,HW,CO) fp32
__device__ float g_v[(size_t)NB*HWP*CO];   // v projection
__device__ float g_x[(size_t)NB*TT*CO];    // x_out, (B,T,CO) fp32
__device__ float g_q[(size_t)NB*TT*CO];    // q / mlp / conv staging

// fp16 split operands
__device__ __align__(16) __half g_ih[(size_t)NB*CIN*HWP];   // x_in hi, K-major [b][c][pix]
__device__ __align__(16) __half g_il[(size_t)NB*CIN*HWP];   // x_in lo
__device__ __align__(16) __half g_ch[(size_t)NB*1024*TT];   // im2col x_in hi [b][c*4+w][t]
__device__ __align__(16) __half g_cl[(size_t)NB*1024*TT];   // im2col lo
__device__ __align__(16) __half g_xh[(size_t)NB*TT*CO];     // x_out hi, M-major [b][t][c]
__device__ __align__(16) __half g_xl[(size_t)NB*TT*CO];     // x_out lo
#define OFF_CONV 0
#define OFF_K    (512*1024)
#define OFF_Q    (OFF_K + 512*256)
#define OFF_V    (OFF_Q + 512*512)
#define OFF_MLP  (OFF_V + 512*256)
#define W_TOTAL  (OFF_MLP + 512*512)
__device__ __align__(16) __half g_wh[W_TOTAL];              // weights hi [n][k] concat
__device__ __align__(16) __half g_wl[W_TOTAL];              // weights lo

// ===========================================================================
// helpers
// ===========================================================================
__device__ __forceinline__ uint32_t smem_to_u32(const void* p) {
    uint32_t a;
    asm("{ .reg .u64 t; cvta.to.shared.u64 t, %1; cvt.u32.u64 %0, t; }"
        : "=r"(a) : "l"(p));
    return a;
}
__device__ __forceinline__ float warp_sum(float v) {
#pragma unroll
    for (int o = 16; o > 0; o >>= 1) v += __shfl_xor_sync(0xffffffffu, v, o);
    return v;
}
__device__ __forceinline__ void mma16816(float* c, const uint32_t* a, const uint32_t* b) {
    asm volatile("mma.sync.aligned.m16n8k16.row.col.f32.f16.f16.f32 "
        "{%0,%1,%2,%3}, {%4,%5,%6,%7}, {%8,%9}, {%0,%1,%2,%3};"
        : "+f"(c[0]), "+f"(c[1]), "+f"(c[2]), "+f"(c[3])
        : "r"(a[0]), "r"(a[1]), "r"(a[2]), "r"(a[3]), "r"(b[0]), "r"(b[1]));
}
__device__ __forceinline__ void ldsm4(uint32_t* r, uint32_t a) {
    asm volatile("ldmatrix.sync.aligned.m8n8.x4.shared.b16 {%0,%1,%2,%3}, [%4];"
        : "=r"(r[0]), "=r"(r[1]), "=r"(r[2]), "=r"(r[3]) : "r"(a));
}
__device__ __forceinline__ void ldsm4t(uint32_t* r, uint32_t a) {
    asm volatile("ldmatrix.sync.aligned.m8n8.x4.trans.shared.b16 {%0,%1,%2,%3}, [%4];"
        : "=r"(r[0]), "=r"(r[1]), "=r"(r[2]), "=r"(r[3]) : "r"(a));
}
__device__ __forceinline__ void cp16(uint32_t sm, const void* g) {
    asm volatile("cp.async.cg.shared.global [%0], [%1], 16;"
        :: "r"(sm), "l"(g) : "memory");
}
__device__ __forceinline__ void cp_commit() {
    asm volatile("cp.async.commit_group;" ::: "memory");
}
template<int N> __device__ __forceinline__ void cp_wait() {
    asm volatile("cp.async.wait_group %0;" :: "n"(N) : "memory");
}
__device__ __forceinline__ void split1f(float x, __half& h, __half& l) {
    h = __float2half_rn(x);
    l = __float2half_rn(x - __half2float(h));
}

// ===========================================================================
// split kernels
// ===========================================================================
__global__ __launch_bounds__(256)
void split_w5(const float* __restrict__ w0, const float* __restrict__ w1,
              const float* __restrict__ w2, const float* __restrict__ w3,
              const float* __restrict__ w4)
{
    int i = blockIdx.x * 256 + threadIdx.x;
    if (i >= W_TOTAL) return;
    const float* s; int off;
    if      (i < OFF_K)   { s = w0; off = i - OFF_CONV; }
    else if (i < OFF_Q)   { s = w1; off = i - OFF_K; }
    else if (i < OFF_V)   { s = w2; off = i - OFF_Q; }
    else if (i < OFF_MLP) { s = w3; off = i - OFF_V; }
    else                  { s = w4; off = i - OFF_MLP; }
    __half h, l; split1f(s[off], h, l);
    g_wh[i] = h; g_wl[i] = l;
}

__global__ __launch_bounds__(256)
void split_xin(const float* __restrict__ x)
{
    int i = blockIdx.x * 256 + threadIdx.x;      // < NB*CIN*HWP
    float v = x[i];
    __half h, l; split1f(v, h, l);
    g_ih[i] = h; g_il[i] = l;
    int p  = i & (HWP - 1);
    int bc = i >> 14;                 // HWP = 2^14
    int b  = bc >> 8, c = bc & 255;   // CIN = 256
    int hr = p >> 7, wc = p & 127;
    int kg = c * 4 + (hr & 1) * 2 + (wc & 1);
    int t  = (hr >> 1) * 64 + (wc >> 1);
    size_t o = ((size_t)b * 1024 + kg) * TT + t;
    g_ch[o] = h; g_cl[o] = l;
}

// ===========================================================================
// HMMA split-fp16 GEMM core pieces (tile 128x128, K-chunk 32, 8 warps 2x4,
// warp tile 64x32, 3-stage cp.async, full A-frag prefetch, term-major MMAs)
// ===========================================================================
#define STAGE   32768
#define SMEMDYN (3*STAGE)

template<int KMAJOR, int K>
__device__ __forceinline__ void gemm_issue(
    uint32_t sb, int s, int c, int tid, int m0, int n0, int M,
    const __half* pAh, const __half* pAl,
    const __half* Bh, const __half* Bl)
{
    const int k0 = c * 32;
    const uint32_t As = sb + s * STAGE;
    const uint32_t Bs = As + 16384;
    if (KMAJOR) {
#pragma unroll
        for (int j = 0; j < 2; j++) {
            int idx = tid + j * 256;
            int r = idx >> 4, ch = idx & 15;
            uint32_t so = r * 256 + ((ch ^ (r & 7)) << 4);
            size_t go = (size_t)(k0 + r) * M + m0 + ch * 8;
            cp16(As + so, pAh + go);
            cp16(As + 8192 + so, pAl + go);
        }
    } else {
#pragma unroll
        for (int j = 0; j < 4; j++) {
            int idx = tid + j * 256;
            int r = idx >> 3, q = idx & 7;
            uint32_t sm = As + r * 128 + ((q ^ (r & 7)) << 4);
            const __half* g = ((q < 4) ? pAh : pAl)
                              + (size_t)(m0 + r) * K + k0 + (q & 3) * 8;
            cp16(sm, g);
        }
    }
#pragma unroll
    for (int j = 0; j < 4; j++) {
        int idx = tid + j * 256;
        int r = idx >> 3, q = idx & 7;
        uint32_t sm = Bs + r * 128 + ((q ^ (r & 7)) << 4);
        const __half* g = ((q < 4) ? Bh : Bl)
                          + (size_t)(n0 + r) * K + k0 + (q & 3) * 8;
        cp16(sm, g);
    }
    cp_commit();
}

template<int KMAJOR>
__device__ __forceinline__ void gemm_compute(
    uint32_t sb, int s, int lane, int wm, int wn, float acc[4][4][4])
{
    const uint32_t As = sb + s * STAGE;
    const uint32_t Bs = As + 16384;
    const int g = lane >> 3;
    const uint32_t l7 = lane & 7;
#pragma unroll
    for (int ks = 0; ks < 2; ++ks) {
        uint32_t bh[8], bl[8], ah[16], al[16];
        {
            uint32_t nrow = wn * 32 + (g >> 1) * 8 + l7;
            uint32_t cH = ((ks * 2 + (g & 1)) ^ l7) << 4;
            uint32_t cL = ((ks * 2 + (g & 1) + 4) ^ l7) << 4;
            uint32_t r0 = Bs + nrow * 128;
            ldsm4(&bh[0], r0 + cH);
            ldsm4(&bl[0], r0 + cL);
            uint32_t r1 = r0 + 16 * 128;
            ldsm4(&bh[4], r1 + cH);
            ldsm4(&bl[4], r1 + cL);
        }
#pragma unroll
        for (int mt = 0; mt < 4; ++mt) {
            if (KMAJOR) {
                uint32_t krow = ks * 16 + (g >> 1) * 8 + l7;
                uint32_t mch = wm * 8 + mt * 2 + (g & 1);
                uint32_t a = As + krow * 256 + ((mch ^ l7) << 4);
                ldsm4t(&ah[mt * 4], a);
                ldsm4t(&al[mt * 4], a + 8192);
            } else {
                uint32_t mrow = wm * 64 + mt * 16 + (g & 1) * 8 + l7;
                uint32_t ch = ks * 2 + (g >> 1);
                uint32_t ra = As + mrow * 128;
                ldsm4(&ah[mt * 4], ra + ((ch ^ l7) << 4));
                ldsm4(&al[mt * 4], ra + (((ch + 4) ^ l7) << 4));
            }
        }
        // term-major sweeps; per-acc order stays hh -> hl -> lh (bit-identical),
        // same-acc RAW distance = 16 MMAs.
#pragma unroll
        for (int mt = 0; mt < 4; ++mt)
#pragma unroll
            for (int nt = 0; nt < 4; ++nt) mma16816(acc[mt][nt], &ah[mt * 4], &bh[nt * 2]);
#pragma unroll
        for (int mt = 0; mt < 4; ++mt)
#pragma unroll
            for (int nt = 0; nt < 4; ++nt) mma16816(acc[mt][nt], &ah[mt * 4], &bl[nt * 2]);
#pragma unroll
        for (int mt = 0; mt < 4; ++mt)
#pragma unroll
            for (int nt = 0; nt < 4; ++nt) mma16816(acc[mt][nt], &al[mt * 4], &bh[nt * 2]);
    }
}

__device__ __forceinline__ void gemm_epilogue(
    float acc[4][4][4], const float* bias, float* C,
    int lane, int wm, int wn, int m0, int n0, size_t bM, int M)
{
    const int gq = lane >> 2, tq = lane & 3;
#pragma unroll
    for (int mt = 0; mt < 4; ++mt) {
        int mrow = m0 + wm * 64 + mt * 16 + gq;
        float* Cr = C + (bM + mrow) * CO + n0;
#pragma unroll
        for (int nt = 0; nt < 4; ++nt) {
            int col = wn * 32 + nt * 8 + tq * 2;
            float b0 = bias[n0 + col], b1 = bias[n0 + col + 1];
            float2 v0; v0.x = acc[mt][nt][0] + b0; v0.y = acc[mt][nt][1] + b1;
            *(float2*)&Cr[col] = v0;
            float2 v1; v1.x = acc[mt][nt][2] + b0; v1.y = acc[mt][nt][3] + b1;
            *(float2*)&Cr[col + 8 * CO] = v1;
        }
    }
}

template<int KMAJOR, int NCH>
__global__ __launch_bounds__(256, 2)
void hgemm(const __half* __restrict__ Ah, const __half* __restrict__ Al,
           const __half* __restrict__ Bh, const __half* __restrict__ Bl,
           const float* __restrict__ bias, float* __restrict__ C,
           int M)
{
    constexpr int K = NCH * 32;
    extern __shared__ char sm_[];
    const uint32_t sb = smem_to_u32(sm_);
    const int tid = threadIdx.x;
    const int lane = tid & 31;
    const int wid = tid >> 5;
    const int wm = wid & 1, wn = wid >> 1;
    const int m0 = blockIdx.x * 128, n0 = blockIdx.y * 128, bz = blockIdx.z;
    const __half* pAh = Ah + (size_t)bz * M * K;
    const __half* pAl = Al + (size_t)bz * M * K;

    float acc[4][4][4];
#pragma unroll
    for (int i = 0; i < 4; i++)
#pragma unroll
        for (int j = 0; j < 4; j++)
#pragma unroll
            for (int r = 0; r < 4; r++) acc[i][j][r] = 0.f;

    gemm_issue<KMAJOR, K>(sb, 0, 0, tid, m0, n0, M, pAh, pAl, Bh, Bl);
    gemm_issue<KMAJOR, K>(sb, 1, 1, tid, m0, n0, M, pAh, pAl, Bh, Bl);
#pragma unroll
    for (int c = 0; c < NCH; ++c) {
        if (c < NCH - 1) cp_wait<1>(); else cp_wait<0>();
        __syncthreads();
        if (c + 2 < NCH) gemm_issue<KMAJOR, K>(sb, (c + 2) % 3, c + 2, tid, m0, n0, M, pAh, pAl, Bh, Bl);
        gemm_compute<KMAJOR>(sb, c % 3, lane, wm, wn, acc);
    }
    gemm_epilogue(acc, bias, C, lane, wm, wn, m0, n0, (size_t)bz * M, M);
}

// k+v fused: grid.y in [0,8); y<4 -> k weights/out, y>=4 -> v. Shared A tiles
// get near-perfect L2 reuse across the 8 N-tiles.
__global__ __launch_bounds__(256, 2)
void hgemm_kv(const __half* __restrict__ Ah, const __half* __restrict__ Al,
              const __half* __restrict__ Bh0, const __half* __restrict__ Bl0,
              const float* __restrict__ bias0, float* __restrict__ C0,
              const __half* __restrict__ Bh1, const __half* __restrict__ Bl1,
              const float* __restrict__ bias1, float* __restrict__ C1,
              int M)
{
    constexpr int K = CIN;          // 256, NCH = 8
    constexpr int NCH = 8;
    extern __shared__ char sm_[];
    const uint32_t sb = smem_to_u32(sm_);
    const int tid = threadIdx.x;
    const int lane = tid & 31;
    const int wid = tid >> 5;
    const int wm = wid & 1, wn = wid >> 1;
    const int m0 = blockIdx.x * 128, n0 = (blockIdx.y & 3) * 128, bz = blockIdx.z;
    const int sec = blockIdx.y >> 2;
    const __half* Bh = sec ? Bh1 : Bh0;
    const __half* Bl = sec ? Bl1 : Bl0;
    const float* bias = sec ? bias1 : bias0;
    float* C = sec ? C1 : C0;
    const __half* pAh = Ah + (size_t)bz * M * K;
    const __half* pAl = Al + (size_t)bz * M * K;

    float acc[4][4][4];
#pragma unroll
    for (int i = 0; i < 4; i++)
#pragma unroll
        for (int j = 0; j < 4; j++)
#pragma unroll
            for (int r = 0; r < 4; r++) acc[i][j][r] = 0.f;

    gemm_issue<1, K>(sb, 0, 0, tid, m0, n0, M, pAh, pAl, Bh, Bl);
    gemm_issue<1, K>(sb, 1, 1, tid, m0, n0, M, pAh, pAl, Bh, Bl);
#pragma unroll
    for (int c = 0; c < NCH; ++c) {
        if (c < NCH - 1) cp_wait<1>(); else cp_wait<0>();
        __syncthreads();
        if (c + 2 < NCH) gemm_issue<1, K>(sb, (c + 2) % 3, c + 2, tid, m0, n0, M, pAh, pAl, Bh, Bl);
        gemm_compute<1>(sb, c % 3, lane, wm, wn, acc);
    }
    gemm_epilogue(acc, bias, C, lane, wm, wn, m0, n0, (size_t)bz * M, M);
}

// ---------------------------------------------------------------------------
// Channel LayerNorm over CO=512; also emits fp16 hi/lo of the result row.
// ---------------------------------------------------------------------------
__global__ __launch_bounds__(256)
void ln_kernel(const float* __restrict__ in, float* __restrict__ xo,
               __half* __restrict__ xh, __half* __restrict__ xl,
               const float* __restrict__ g, const float* __restrict__ bvec, int add)
{
    const int tid = threadIdx.x;
    const size_t row = blockIdx.x;
    const float* r = in + row * CO;
    float v0 = r[tid], v1 = r[tid + 256];
    float s  = v0 + v1;
    float s2 = v0 * v0 + v1 * v1;
    s  = warp_sum(s);
    s2 = warp_sum(s2);
    __shared__ float r1[8], r2[8];
    const int lane = tid & 31, warp = tid >> 5;
    if (lane == 0) { r1[warp] = s; r2[warp] = s2; }
    __syncthreads();
    float ss = 0.f, sq = 0.f;
#pragma unroll
    for (int i = 0; i < 8; i++) { ss += r1[i]; sq += r2[i]; }
    float mu  = ss / CO;
    float var = sq / CO - mu * mu;
    float rs  = rsqrtf(var + EPSF);
    float o0 = (v0 - mu) * rs * g[tid]       + bvec[tid];
    float o1 = (v1 - mu) * rs * g[tid + 256] + bvec[tid + 256];
    float* xr = xo + row * CO;
    float f0, f1;
    if (add) { f0 = xr[tid] + o0; f1 = xr[tid + 256] + o1; }
    else     { f0 = o0;           f1 = o1; }
    xr[tid] = f0; xr[tid + 256] = f1;
    __half h, l;
    split1f(f0, h, l); xh[row * CO + tid] = h;       xl[row * CO + tid] = l;
    split1f(f1, h, l); xh[row * CO + tid + 256] = h; xl[row * CO + tid + 256] = l;
}

// ---------------------------------------------------------------------------
// Fused attention step; also emits fp16 hi/lo of the updated x row.
// ---------------------------------------------------------------------------
__global__ __launch_bounds__(256)
void att_kernel(const float* __restrict__ qb, const float* __restrict__ kb,
                const float* __restrict__ vb, float* __restrict__ xb,
                __half* __restrict__ xh, __half* __restrict__ xl,
                const float* __restrict__ lg, const float* __restrict__ lb)
{
    const int tid = threadIdx.x;
    const int row = blockIdx.x;            // b*T + t
    const int b = row >> 12;
    const int t = row & (TT - 1);
    const int ho = t >> 6, wo = t & 63;
    const int pix0 = (ho << 1) * WW + (wo << 1);
    const size_t base = ((size_t)b * HWP + pix0) * CO;
    const float* kp = kb + base;
    const float* vp = vb + base;
    const float* qr = qb + (size_t)row * CO;

    const size_t S1 = CO;
    const size_t S2 = (size_t)WW * CO;
    const size_t S3 = S2 + CO;

    float q0 = qr[tid], q1 = qr[tid + 256];
    float d0 = q0 * kp[tid]      + q1 * kp[tid + 256];
    float d1 = q0 * kp[S1 + tid] + q1 * kp[S1 + tid + 256];
    float d2 = q0 * kp[S2 + tid] + q1 * kp[S2 + tid + 256];
    float d3 = q0 * kp[S3 + tid] + q1 * kp[S3 + tid + 256];
    d0 = warp_sum(d0); d1 = warp_sum(d1); d2 = warp_sum(d2); d3 = warp_sum(d3);

    __shared__ float red[4][8];
    __shared__ float r1[8], r2[8];
    const int lane = tid & 31, warp = tid >> 5;
    if (lane == 0) { red[0][warp] = d0; red[1][warp] = d1;
                     red[2][warp] = d2; red[3][warp] = d3; }
    __syncthreads();
    float a0 = 0.f, a1 = 0.f, a2 = 0.f, a3 = 0.f;
#pragma unroll
    for (int i = 0; i < 8; i++) {
        a0 += red[0][i]; a1 += red[1][i]; a2 += red[2][i]; a3 += red[3][i];
    }
    float mx = fmaxf(fmaxf(a0, a1), fmaxf(a2, a3));
    float e0 = __expf(a0 - mx), e1 = __expf(a1 - mx);
    float e2 = __expf(a2 - mx), e3 = __expf(a3 - mx);
    float inv = 1.f / (e0 + e1 + e2 + e3);
    e0 *= inv; e1 *= inv; e2 *= inv; e3 *= inv;

    float u0 = e0 * vp[tid]       + e1 * vp[S1 + tid]
             + e2 * vp[S2 + tid]  + e3 * vp[S3 + tid];
    float u1 = e0 * vp[tid + 256]      + e1 * vp[S1 + tid + 256]
             + e2 * vp[S2 + tid + 256] + e3 * vp[S3 + tid + 256];

    float s  = u0 + u1;
    float s2 = u0 * u0 + u1 * u1;
    s  = warp_sum(s);
    s2 = warp_sum(s2);
    if (lane == 0) { r1[warp] = s; r2[warp] = s2; }
    __syncthreads();
    float ss = 0.f, sq = 0.f;
#pragma unroll
    for (int i = 0; i < 8; i++) { ss += r1[i]; sq += r2[i]; }
    float mu  = ss / CO;
    float var = sq / CO - mu * mu;
    float rs  = rsqrtf(var + EPSF);

    float* xo = xb + (size_t)row * CO;
    float f0 = xo[tid]       + (u0 - mu) * rs * lg[tid]       + lb[tid];
    float f1 = xo[tid + 256] + (u1 - mu) * rs * lg[tid + 256] + lb[tid + 256];
    xo[tid] = f0; xo[tid + 256] = f1;
    __half h, l;
    split1f(f0, h, l); xh[(size_t)row * CO + tid] = h;       xl[(size_t)row * CO + tid] = l;
    split1f(f1, h, l); xh[(size_t)row * CO + tid + 256] = h; xl[(size_t)row * CO + tid + 256] = l;
}

// ---------------------------------------------------------------------------
// Final transpose (B,T,CO) pixel-major -> NCHW output (B,CO,64,64)
// ---------------------------------------------------------------------------
__global__ void transpose_kernel(const float* __restrict__ x, float* __restrict__ out)
{
    __shared__ float tile[32][33];
    const int b  = blockIdx.z;
    const int t0 = blockIdx.x * 32;
    const int f0 = blockIdx.y * 32;
    const int tx = threadIdx.x, ty = threadIdx.y;
#pragma unroll
    for (int j = 0; j < 32; j += 8)
        tile[ty + j][tx] = x[((size_t)b * TT + t0 + ty + j) * CO + f0 + tx];
    __syncthreads();
#pragma unroll
    for (int j = 0; j < 32; j += 8)
        out[((size_t)b * CO + f0 + ty + j) * TT + t0 + tx] = tile[tx][ty + j];
}

// ---------------------------------------------------------------------------
extern "C" void kernel_launch(void* const* d_in, const int* in_sizes, int n_in,
                              void* d_out, int out_size)
{
    const float* x_in   = (const float*)d_in[0];
    const float* conv_w = (const float*)d_in[1];
    const float* conv_b = (const float*)d_in[2];
    const float* k_w    = (const float*)d_in[3];
    const float* k_b    = (const float*)d_in[4];
    const float* q_w    = (const float*)d_in[5];
    const float* q_b    = (const float*)d_in[6];
    const float* v_w    = (const float*)d_in[7];
    const float* v_b    = (const float*)d_in[8];
    const float* mlp_w  = (const float*)d_in[9];
    const float* mlp_b  = (const float*)d_in[10];
    const float* lnc_g  = (const float*)d_in[11];
    const float* lnc_b  = (const float*)d_in[12];
    const float* lnv_g  = (const float*)d_in[13];
    const float* lnv_b  = (const float*)d_in[14];
    const float* lnm_g  = (const float*)d_in[15];
    const float* lnm_b  = (const float*)d_in[16];
    float* out = (float*)d_out;

    float *pk, *pv, *px, *pq;
    __half *ih, *il, *ch, *cl, *xh, *xl, *wh, *wl;
    cudaGetSymbolAddress((void**)&pk, g_k);
    cudaGetSymbolAddress((void**)&pv, g_v);
    cudaGetSymbolAddress((void**)&px, g_x);
    cudaGetSymbolAddress((void**)&pq, g_q);
    cudaGetSymbolAddress((void**)&ih, g_ih);
    cudaGetSymbolAddress((void**)&il, g_il);
    cudaGetSymbolAddress((void**)&ch, g_ch);
    cudaGetSymbolAddress((void**)&cl, g_cl);
    cudaGetSymbolAddress((void**)&xh, g_xh);
    cudaGetSymbolAddress((void**)&xl, g_xl);
    cudaGetSymbolAddress((void**)&wh, g_wh);
    cudaGetSymbolAddress((void**)&wl, g_wl);

    cudaFuncSetAttribute(hgemm<1,32>, cudaFuncAttributeMaxDynamicSharedMemorySize, SMEMDYN);
    cudaFuncSetAttribute(hgemm_kv,    cudaFuncAttributeMaxDynamicSharedMemorySize, SMEMDYN);
    cudaFuncSetAttribute(hgemm<0,16>, cudaFuncAttributeMaxDynamicSharedMemorySize, SMEMDYN);

    // launch order arranged so ncu (-s 5 -c 1) captures launch #6 = q GEMM.
    // 1) split weights (single launch) + 2) split input
    split_w5<<<(W_TOTAL + 255) / 256, 256>>>(conv_w, k_w, q_w, v_w, mlp_w);
    split_xin<<<NB * CIN * HWP / 256, 256>>>(x_in);

    const dim3 gq(TT / 128, CO / 128, NB);     // conv/q/mlp GEMMs
    const dim3 gkv(HWP / 128, 8, NB);          // fused k+v GEMM

    // 3) k+v fused projection
    hgemm_kv<<<gkv, 256, SMEMDYN>>>(ih, il,
        wh + OFF_K, wl + OFF_K, k_b, pk,
        wh + OFF_V, wl + OFF_V, v_b, pv, HWP);

    // 4) patchify conv (K-major im2col) -> staging, 5) channel LN -> x_out
    hgemm<1,32><<<gq, 256, SMEMDYN>>>(ch, cl, wh + OFF_CONV, wl + OFF_CONV, conv_b, pq, TT);
    ln_kernel<<<NB * TT, 256>>>(pq, px, xh, xl, lnc_g, lnc_b, 0);

    // 6+) iterative grouping
    for (int it = 0; it < ITERS; it++) {
        hgemm<0,16><<<gq, 256, SMEMDYN>>>(xh, xl, wh + OFF_Q, wl + OFF_Q, q_b, pq, TT);
        att_kernel<<<NB * TT, 256>>>(pq, pk, pv, px, xh, xl, lnv_g, lnv_b);
        hgemm<0,16><<<gq, 256, SMEMDYN>>>(xh, xl, wh + OFF_MLP, wl + OFF_MLP, mlp_b, pq, TT);
        ln_kernel<<<NB * TT, 256>>>(pq, px, xh, xl, lnm_g, lnm_b, 1);
    }

    // final transpose to NCHW
    transpose_kernel<<<dim3(TT / 32, CO / 32, NB), dim3(32, 8)>>>(px, out);
}

// round 7
// speedup vs baseline: 2.5579x; 1.0481x over previous
#include <cuda_runtime.h>
#include <cuda_fp16.h>
#include <cstdint>

// Problem constants
#define NB   4
#define CIN  256
#define HH   128
#define WW   128
#define HWP  (HH*WW)      // 16384
#define CO   512
#define TT   4096         // 64*64 output pixels
#define EPSF 1e-5f
#define ITERS 3

// ---------------------------------------------------------------------------
// Scratch
// ---------------------------------------------------------------------------
__device__ float g_k[(size_t)NB*HWP*CO];   // k projection, (B,HW,CO) fp32
__device__ float g_v[(size_t)NB*HWP*CO];   // v projection
__device__ float g_x[(size_t)NB*TT*CO];    // x_out, (B,T,CO) fp32
__device__ float g_q[(size_t)NB*TT*CO];    // q / mlp / conv staging

// fp16 split operands
__device__ __align__(16) __half g_ih[(size_t)NB*CIN*HWP];   // x_in hi, K-major [b][c][pix]
__device__ __align__(16) __half g_il[(size_t)NB*CIN*HWP];   // x_in lo
__device__ __align__(16) __half g_ch[(size_t)NB*1024*TT];   // im2col x_in hi [b][c*4+w][t]
__device__ __align__(16) __half g_cl[(size_t)NB*1024*TT];   // im2col lo
__device__ __align__(16) __half g_xh[(size_t)NB*TT*CO];     // x_out hi, M-major [b][t][c]
__device__ __align__(16) __half g_xl[(size_t)NB*TT*CO];     // x_out lo
#define OFF_CONV 0
#define OFF_K    (512*1024)
#define OFF_Q    (OFF_K + 512*256)
#define OFF_V    (OFF_Q + 512*512)
#define OFF_MLP  (OFF_V + 512*256)
#define W_TOTAL  (OFF_MLP + 512*512)
__device__ __align__(16) __half g_wh[W_TOTAL];              // weights hi [n][k] concat
__device__ __align__(16) __half g_wl[W_TOTAL];              // weights lo

// ===========================================================================
// helpers
// ===========================================================================
__device__ __forceinline__ uint32_t smem_to_u32(const void* p) {
    uint32_t a;
    asm("{ .reg .u64 t; cvta.to.shared.u64 t, %1; cvt.u32.u64 %0, t; }"
        : "=r"(a) : "l"(p));
    return a;
}
__device__ __forceinline__ float warp_sum(float v) {
#pragma unroll
    for (int o = 16; o > 0; o >>= 1) v += __shfl_xor_sync(0xffffffffu, v, o);
    return v;
}
// NOTE: non-volatile on purpose — pure register op, lets ptxas interleave
// with ldmatrix to hide latency. Data deps keep per-acc order bit-identical.
__device__ __forceinline__ void mma16816(float* c, const uint32_t* a, const uint32_t* b) {
    asm("mma.sync.aligned.m16n8k16.row.col.f32.f16.f16.f32 "
        "{%0,%1,%2,%3}, {%4,%5,%6,%7}, {%8,%9}, {%0,%1,%2,%3};"
        : "+f"(c[0]), "+f"(c[1]), "+f"(c[2]), "+f"(c[3])
        : "r"(a[0]), "r"(a[1]), "r"(a[2]), "r"(a[3]), "r"(b[0]), "r"(b[1]));
}
// non-volatile but "memory"-clobbered: can't cross barriers/cp.async, CAN
// float among MMAs.
__device__ __forceinline__ void ldsm4(uint32_t* r, uint32_t a) {
    asm("ldmatrix.sync.aligned.m8n8.x4.shared.b16 {%0,%1,%2,%3}, [%4];"
        : "=r"(r[0]), "=r"(r[1]), "=r"(r[2]), "=r"(r[3]) : "r"(a) : "memory");
}
__device__ __forceinline__ void ldsm4t(uint32_t* r, uint32_t a) {
    asm("ldmatrix.sync.aligned.m8n8.x4.trans.shared.b16 {%0,%1,%2,%3}, [%4];"
        : "=r"(r[0]), "=r"(r[1]), "=r"(r[2]), "=r"(r[3]) : "r"(a) : "memory");
}
__device__ __forceinline__ void cp16(uint32_t sm, const void* g) {
    asm volatile("cp.async.cg.shared.global [%0], [%1], 16;"
        :: "r"(sm), "l"(g) : "memory");
}
__device__ __forceinline__ void cp_commit() {
    asm volatile("cp.async.commit_group;" ::: "memory");
}
template<int N> __device__ __forceinline__ void cp_wait() {
    asm volatile("cp.async.wait_group %0;" :: "n"(N) : "memory");
}
__device__ __forceinline__ void split1f(float x, __half& h, __half& l) {
    h = __float2half_rn(x);
    l = __float2half_rn(x - __half2float(h));
}
// split float4 -> hi uint2 (4 halves) + lo uint2
__device__ __forceinline__ void split4f(float4 f, uint2& H, uint2& L) {
    __half h[4], l[4];
    split1f(f.x, h[0], l[0]); split1f(f.y, h[1], l[1]);
    split1f(f.z, h[2], l[2]); split1f(f.w, h[3], l[3]);
    __half2 h0 = __halves2half2(h[0], h[1]), h1 = __halves2half2(h[2], h[3]);
    __half2 l0 = __halves2half2(l[0], l[1]), l1 = __halves2half2(l[2], l[3]);
    H.x = *(uint32_t*)&h0; H.y = *(uint32_t*)&h1;
    L.x = *(uint32_t*)&l0; L.y = *(uint32_t*)&l1;
}

// ===========================================================================
// split kernels
// ===========================================================================
__global__ __launch_bounds__(256)
void split_w5(const float* __restrict__ w0, const float* __restrict__ w1,
              const float* __restrict__ w2, const float* __restrict__ w3,
              const float* __restrict__ w4)
{
    int i = blockIdx.x * 256 + threadIdx.x;
    if (i >= W_TOTAL) return;
    const float* s; int off;
    if      (i < OFF_K)   { s = w0; off = i - OFF_CONV; }
    else if (i < OFF_Q)   { s = w1; off = i - OFF_K; }
    else if (i < OFF_V)   { s = w2; off = i - OFF_Q; }
    else if (i < OFF_MLP) { s = w3; off = i - OFF_V; }
    else                  { s = w4; off = i - OFF_MLP; }
    __half h, l; split1f(s[off], h, l);
    g_wh[i] = h; g_wl[i] = l;
}

__global__ __launch_bounds__(256)
void split_xin(const float* __restrict__ x)
{
    int i = blockIdx.x * 256 + threadIdx.x;      // < NB*CIN*HWP
    float v = x[i];
    __half h, l; split1f(v, h, l);
    g_ih[i] = h; g_il[i] = l;
    int p  = i & (HWP - 1);
    int bc = i >> 14;                 // HWP = 2^14
    int b  = bc >> 8, c = bc & 255;   // CIN = 256
    int hr = p >> 7, wc = p & 127;
    int kg = c * 4 + (hr & 1) * 2 + (wc & 1);
    int t  = (hr >> 1) * 64 + (wc >> 1);
    size_t o = ((size_t)b * 1024 + kg) * TT + t;
    g_ch[o] = h; g_cl[o] = l;
}

// ===========================================================================
// HMMA split-fp16 GEMM core pieces (tile 128x128, K-chunk 32, 8 warps 2x4,
// warp tile 64x32, 3-stage cp.async, full A-frag prefetch, term-major MMAs)
// ===========================================================================
#define STAGE   32768
#define SMEMDYN (3*STAGE)

template<int KMAJOR, int K>
__device__ __forceinline__ void gemm_issue(
    uint32_t sb, int s, int c, int tid, int m0, int n0, int M,
    const __half* pAh, const __half* pAl,
    const __half* Bh, const __half* Bl)
{
    const int k0 = c * 32;
    const uint32_t As = sb + s * STAGE;
    const uint32_t Bs = As + 16384;
    if (KMAJOR) {
#pragma unroll
        for (int j = 0; j < 2; j++) {
            int idx = tid + j * 256;
            int r = idx >> 4, ch = idx & 15;
            uint32_t so = r * 256 + ((ch ^ (r & 7)) << 4);
            size_t go = (size_t)(k0 + r) * M + m0 + ch * 8;
            cp16(As + so, pAh + go);
            cp16(As + 8192 + so, pAl + go);
        }
    } else {
#pragma unroll
        for (int j = 0; j < 4; j++) {
            int idx = tid + j * 256;
            int r = idx >> 3, q = idx & 7;
            uint32_t sm = As + r * 128 + ((q ^ (r & 7)) << 4);
            const __half* g = ((q < 4) ? pAh : pAl)
                              + (size_t)(m0 + r) * K + k0 + (q & 3) * 8;
            cp16(sm, g);
        }
    }
#pragma unroll
    for (int j = 0; j < 4; j++) {
        int idx = tid + j * 256;
        int r = idx >> 3, q = idx & 7;
        uint32_t sm = Bs + r * 128 + ((q ^ (r & 7)) << 4);
        const __half* g = ((q < 4) ? Bh : Bl)
                          + (size_t)(n0 + r) * K + k0 + (q & 3) * 8;
        cp16(sm, g);
    }
    cp_commit();
}

template<int KMAJOR>
__device__ __forceinline__ void gemm_compute(
    uint32_t sb, int s, int lane, int wm, int wn, float acc[4][4][4])
{
    const uint32_t As = sb + s * STAGE;
    const uint32_t Bs = As + 16384;
    const int g = lane >> 3;
    const uint32_t l7 = lane & 7;
#pragma unroll
    for (int ks = 0; ks < 2; ++ks) {
        uint32_t bh[8], bl[8], ah[16], al[16];
        {
            uint32_t nrow = wn * 32 + (g >> 1) * 8 + l7;
            uint32_t cH = ((ks * 2 + (g & 1)) ^ l7) << 4;
            uint32_t cL = ((ks * 2 + (g & 1) + 4) ^ l7) << 4;
            uint32_t r0 = Bs + nrow * 128;
            ldsm4(&bh[0], r0 + cH);
            ldsm4(&bl[0], r0 + cL);
            uint32_t r1 = r0 + 16 * 128;
            ldsm4(&bh[4], r1 + cH);
            ldsm4(&bl[4], r1 + cL);
        }
#pragma unroll
        for (int mt = 0; mt < 4; ++mt) {
            if (KMAJOR) {
                uint32_t krow = ks * 16 + (g >> 1) * 8 + l7;
                uint32_t mch = wm * 8 + mt * 2 + (g & 1);
                uint32_t a = As + krow * 256 + ((mch ^ l7) << 4);
                ldsm4t(&ah[mt * 4], a);
                ldsm4t(&al[mt * 4], a + 8192);
            } else {
                uint32_t mrow = wm * 64 + mt * 16 + (g & 1) * 8 + l7;
                uint32_t ch = ks * 2 + (g >> 1);
                uint32_t ra = As + mrow * 128;
                ldsm4(&ah[mt * 4], ra + ((ch ^ l7) << 4));
                ldsm4(&al[mt * 4], ra + (((ch + 4) ^ l7) << 4));
            }
        }
        // term-major sweeps; per-acc order stays hh -> hl -> lh (bit-identical),
        // same-acc RAW distance = 16 MMAs; ptxas free to interleave ldsm.
#pragma unroll
        for (int mt = 0; mt < 4; ++mt)
#pragma unroll
            for (int nt = 0; nt < 4; ++nt) mma16816(acc[mt][nt], &ah[mt * 4], &bh[nt * 2]);
#pragma unroll
        for (int mt = 0; mt < 4; ++mt)
#pragma unroll
            for (int nt = 0; nt < 4; ++nt) mma16816(acc[mt][nt], &ah[mt * 4], &bl[nt * 2]);
#pragma unroll
        for (int mt = 0; mt < 4; ++mt)
#pragma unroll
            for (int nt = 0; nt < 4; ++nt) mma16816(acc[mt][nt], &al[mt * 4], &bh[nt * 2]);
    }
}

__device__ __forceinline__ void gemm_epilogue(
    float acc[4][4][4], const float* bias, float* C,
    int lane, int wm, int wn, int m0, int n0, size_t bM, int M)
{
    const int gq = lane >> 2, tq = lane & 3;
#pragma unroll
    for (int mt = 0; mt < 4; ++mt) {
        int mrow = m0 + wm * 64 + mt * 16 + gq;
        float* Cr = C + (bM + mrow) * CO + n0;
#pragma unroll
        for (int nt = 0; nt < 4; ++nt) {
            int col = wn * 32 + nt * 8 + tq * 2;
            float b0 = bias[n0 + col], b1 = bias[n0 + col + 1];
            float2 v0; v0.x = acc[mt][nt][0] + b0; v0.y = acc[mt][nt][1] + b1;
            *(float2*)&Cr[col] = v0;
            float2 v1; v1.x = acc[mt][nt][2] + b0; v1.y = acc[mt][nt][3] + b1;
            *(float2*)&Cr[col + 8 * CO] = v1;
        }
    }
}

template<int KMAJOR, int NCH>
__global__ __launch_bounds__(256, 2)
void hgemm(const __half* __restrict__ Ah, const __half* __restrict__ Al,
           const __half* __restrict__ Bh, const __half* __restrict__ Bl,
           const float* __restrict__ bias, float* __restrict__ C,
           int M)
{
    constexpr int K = NCH * 32;
    extern __shared__ char sm_[];
    const uint32_t sb = smem_to_u32(sm_);
    const int tid = threadIdx.x;
    const int lane = tid & 31;
    const int wid = tid >> 5;
    const int wm = wid & 1, wn = wid >> 1;
    const int m0 = blockIdx.x * 128, n0 = blockIdx.y * 128, bz = blockIdx.z;
    const __half* pAh = Ah + (size_t)bz * M * K;
    const __half* pAl = Al + (size_t)bz * M * K;

    float acc[4][4][4];
#pragma unroll
    for (int i = 0; i < 4; i++)
#pragma unroll
        for (int j = 0; j < 4; j++)
#pragma unroll
            for (int r = 0; r < 4; r++) acc[i][j][r] = 0.f;

    gemm_issue<KMAJOR, K>(sb, 0, 0, tid, m0, n0, M, pAh, pAl, Bh, Bl);
    gemm_issue<KMAJOR, K>(sb, 1, 1, tid, m0, n0, M, pAh, pAl, Bh, Bl);
#pragma unroll
    for (int c = 0; c < NCH; ++c) {
        if (c < NCH - 1) cp_wait<1>(); else cp_wait<0>();
        __syncthreads();
        if (c + 2 < NCH) gemm_issue<KMAJOR, K>(sb, (c + 2) % 3, c + 2, tid, m0, n0, M, pAh, pAl, Bh, Bl);
        gemm_compute<KMAJOR>(sb, c % 3, lane, wm, wn, acc);
    }
    gemm_epilogue(acc, bias, C, lane, wm, wn, m0, n0, (size_t)bz * M, M);
}

// k+v fused: grid.y in [0,8); y<4 -> k weights/out, y>=4 -> v.
__global__ __launch_bounds__(256, 2)
void hgemm_kv(const __half* __restrict__ Ah, const __half* __restrict__ Al,
              const __half* __restrict__ Bh0, const __half* __restrict__ Bl0,
              const float* __restrict__ bias0, float* __restrict__ C0,
              const __half* __restrict__ Bh1, const __half* __restrict__ Bl1,
              const float* __restrict__ bias1, float* __restrict__ C1,
              int M)
{
    constexpr int K = CIN;          // 256, NCH = 8
    constexpr int NCH = 8;
    extern __shared__ char sm_[];
    const uint32_t sb = smem_to_u32(sm_);
    const int tid = threadIdx.x;
    const int lane = tid & 31;
    const int wid = tid >> 5;
    const int wm = wid & 1, wn = wid >> 1;
    const int m0 = blockIdx.x * 128, n0 = (blockIdx.y & 3) * 128, bz = blockIdx.z;
    const int sec = blockIdx.y >> 2;
    const __half* Bh = sec ? Bh1 : Bh0;
    const __half* Bl = sec ? Bl1 : Bl0;
    const float* bias = sec ? bias1 : bias0;
    float* C = sec ? C1 : C0;
    const __half* pAh = Ah + (size_t)bz * M * K;
    const __half* pAl = Al + (size_t)bz * M * K;

    float acc[4][4][4];
#pragma unroll
    for (int i = 0; i < 4; i++)
#pragma unroll
        for (int j = 0; j < 4; j++)
#pragma unroll
            for (int r = 0; r < 4; r++) acc[i][j][r] = 0.f;

    gemm_issue<1, K>(sb, 0, 0, tid, m0, n0, M, pAh, pAl, Bh, Bl);
    gemm_issue<1, K>(sb, 1, 1, tid, m0, n0, M, pAh, pAl, Bh, Bl);
#pragma unroll
    for (int c = 0; c < NCH; ++c) {
        if (c < NCH - 1) cp_wait<1>(); else cp_wait<0>();
        __syncthreads();
        if (c + 2 < NCH) gemm_issue<1, K>(sb, (c + 2) % 3, c + 2, tid, m0, n0, M, pAh, pAl, Bh, Bl);
        gemm_compute<1>(sb, c % 3, lane, wm, wn, acc);
    }
    gemm_epilogue(acc, bias, C, lane, wm, wn, m0, n0, (size_t)bz * M, M);
}

// ---------------------------------------------------------------------------
// Channel LayerNorm over CO=512, float4-vectorized, 128 threads/row.
// Also emits fp16 hi/lo of the result row.
// ---------------------------------------------------------------------------
__global__ __launch_bounds__(128)
void ln_kernel(const float* __restrict__ in, float* __restrict__ xo,
               __half* __restrict__ xh, __half* __restrict__ xl,
               const float* __restrict__ g, const float* __restrict__ bvec, int add)
{
    const int tid = threadIdx.x;
    const size_t row = blockIdx.x;
    float4 v = ((const float4*)(in + row * CO))[tid];
    float s  = v.x + v.y + v.z + v.w;
    float s2 = v.x * v.x + v.y * v.y + v.z * v.z + v.w * v.w;
    s  = warp_sum(s);
    s2 = warp_sum(s2);
    __shared__ float r1[4], r2[4];
    const int lane = tid & 31, warp = tid >> 5;
    if (lane == 0) { r1[warp] = s; r2[warp] = s2; }
    __syncthreads();
    float ss = r1[0] + r1[1] + r1[2] + r1[3];
    float sq = r2[0] + r2[1] + r2[2] + r2[3];
    float mu  = ss / CO;
    float var = sq / CO - mu * mu;
    float rs  = rsqrtf(var + EPSF);
    float4 g4 = ((const float4*)g)[tid];
    float4 b4 = ((const float4*)bvec)[tid];
    float4 f;
    f.x = (v.x - mu) * rs * g4.x + b4.x;
    f.y = (v.y - mu) * rs * g4.y + b4.y;
    f.z = (v.z - mu) * rs * g4.z + b4.z;
    f.w = (v.w - mu) * rs * g4.w + b4.w;
    float4* xr = (float4*)(xo + row * CO);
    if (add) {
        float4 o = xr[tid];
        f.x += o.x; f.y += o.y; f.z += o.z; f.w += o.w;
    }
    xr[tid] = f;
    uint2 H, L; split4f(f, H, L);
    ((uint2*)(xh + row * CO))[tid] = H;
    ((uint2*)(xl + row * CO))[tid] = L;
}

// ---------------------------------------------------------------------------
// Fused attention step, float4-vectorized, 128 threads/row.
// ---------------------------------------------------------------------------
__global__ __launch_bounds__(128)
void att_kernel(const float* __restrict__ qb, const float* __restrict__ kb,
                const float* __restrict__ vb, float* __restrict__ xb,
                __half* __restrict__ xh, __half* __restrict__ xl,
                const float* __restrict__ lg, const float* __restrict__ lb)
{
    const int tid = threadIdx.x;
    const int row = blockIdx.x;            // b*T + t
    const int b = row >> 12;
    const int t = row & (TT - 1);
    const int ho = t >> 6, wo = t & 63;
    const int pix0 = (ho << 1) * WW + (wo << 1);
    const size_t base = ((size_t)b * HWP + pix0) * CO;
    const float4* kp = (const float4*)(kb + base);
    const float4* vp = (const float4*)(vb + base);
    const float4  q  = ((const float4*)(qb + (size_t)row * CO))[tid];

    const int S1 = CO / 4;                 // (0,1)
    const int S2 = WW * CO / 4;            // (1,0)
    const int S3 = S2 + CO / 4;            // (1,1)

    float4 k0 = kp[tid], k1 = kp[S1 + tid], k2 = kp[S2 + tid], k3 = kp[S3 + tid];
    float d0 = q.x * k0.x + q.y * k0.y + q.z * k0.z + q.w * k0.w;
    float d1 = q.x * k1.x + q.y * k1.y + q.z * k1.z + q.w * k1.w;
    float d2 = q.x * k2.x + q.y * k2.y + q.z * k2.z + q.w * k2.w;
    float d3 = q.x * k3.x + q.y * k3.y + q.z * k3.z + q.w * k3.w;
    d0 = warp_sum(d0); d1 = warp_sum(d1); d2 = warp_sum(d2); d3 = warp_sum(d3);

    __shared__ float red[4][4];
    __shared__ float r1[4], r2[4];
    const int lane = tid & 31, warp = tid >> 5;
    if (lane == 0) { red[0][warp] = d0; red[1][warp] = d1;
                     red[2][warp] = d2; red[3][warp] = d3; }
    __syncthreads();
    float a0 = red[0][0] + red[0][1] + red[0][2] + red[0][3];
    float a1 = red[1][0] + red[1][1] + red[1][2] + red[1][3];
    float a2 = red[2][0] + red[2][1] + red[2][2] + red[2][3];
    float a3 = red[3][0] + red[3][1] + red[3][2] + red[3][3];
    float mx = fmaxf(fmaxf(a0, a1), fmaxf(a2, a3));
    float e0 = __expf(a0 - mx), e1 = __expf(a1 - mx);
    float e2 = __expf(a2 - mx), e3 = __expf(a3 - mx);
    float inv = 1.f / (e0 + e1 + e2 + e3);
    e0 *= inv; e1 *= inv; e2 *= inv; e3 *= inv;

    float4 v0 = vp[tid], v1 = vp[S1 + tid], v2 = vp[S2 + tid], v3 = vp[S3 + tid];
    float4 u;
    u.x = e0 * v0.x + e1 * v1.x + e2 * v2.x + e3 * v3.x;
    u.y = e0 * v0.y + e1 * v1.y + e2 * v2.y + e3 * v3.y;
    u.z = e0 * v0.z + e1 * v1.z + e2 * v2.z + e3 * v3.z;
    u.w = e0 * v0.w + e1 * v1.w + e2 * v2.w + e3 * v3.w;

    float s  = u.x + u.y + u.z + u.w;
    float s2 = u.x * u.x + u.y * u.y + u.z * u.z + u.w * u.w;
    s  = warp_sum(s);
    s2 = warp_sum(s2);
    if (lane == 0) { r1[warp] = s; r2[warp] = s2; }
    __syncthreads();
    float ss = r1[0] + r1[1] + r1[2] + r1[3];
    float sq = r2[0] + r2[1] + r2[2] + r2[3];
    float mu  = ss / CO;
    float var = sq / CO - mu * mu;
    float rs  = rsqrtf(var + EPSF);

    float4 g4 = ((const float4*)lg)[tid];
    float4 b4 = ((const float4*)lb)[tid];
    float4* xr = (float4*)(xb + (size_t)row * CO);
    float4 o = xr[tid];
    float4 f;
    f.x = o.x + (u.x - mu) * rs * g4.x + b4.x;
    f.y = o.y + (u.y - mu) * rs * g4.y + b4.y;
    f.z = o.z + (u.z - mu) * rs * g4.z + b4.z;
    f.w = o.w + (u.w - mu) * rs * g4.w + b4.w;
    xr[tid] = f;
    uint2 H, L; split4f(f, H, L);
    ((uint2*)(xh + (size_t)row * CO))[tid] = H;
    ((uint2*)(xl + (size_t)row * CO))[tid] = L;
}

// ---------------------------------------------------------------------------
// Final transpose (B,T,CO) pixel-major -> NCHW output (B,CO,64,64)
// ---------------------------------------------------------------------------
__global__ void transpose_kernel(const float* __restrict__ x, float* __restrict__ out)
{
    __shared__ float tile[32][33];
    const int b  = blockIdx.z;
    const int t0 = blockIdx.x * 32;
    const int f0 = blockIdx.y * 32;
    const int tx = threadIdx.x, ty = threadIdx.y;
#pragma unroll
    for (int j = 0; j < 32; j += 8)
        tile[ty + j][tx] = x[((size_t)b * TT + t0 + ty + j) * CO + f0 + tx];
    __syncthreads();
#pragma unroll
    for (int j = 0; j < 32; j += 8)
        out[((size_t)b * CO + f0 + ty + j) * TT + t0 + tx] = tile[tx][ty + j];
}

// ---------------------------------------------------------------------------
extern "C" void kernel_launch(void* const* d_in, const int* in_sizes, int n_in,
                              void* d_out, int out_size)
{
    const float* x_in   = (const float*)d_in[0];
    const float* conv_w = (const float*)d_in[1];
    const float* conv_b = (const float*)d_in[2];
    const float* k_w    = (const float*)d_in[3];
    const float* k_b    = (const float*)d_in[4];
    const float* q_w    = (const float*)d_in[5];
    const float* q_b    = (const float*)d_in[6];
    const float* v_w    = (const float*)d_in[7];
    const float* v_b    = (const float*)d_in[8];
    const float* mlp_w  = (const float*)d_in[9];
    const float* mlp_b  = (const float*)d_in[10];
    const float* lnc_g  = (const float*)d_in[11];
    const float* lnc_b  = (const float*)d_in[12];
    const float* lnv_g  = (const float*)d_in[13];
    const float* lnv_b  = (const float*)d_in[14];
    const float* lnm_g  = (const float*)d_in[15];
    const float* lnm_b  = (const float*)d_in[16];
    float* out = (float*)d_out;

    float *pk, *pv, *px, *pq;
    __half *ih, *il, *ch, *cl, *xh, *xl, *wh, *wl;
    cudaGetSymbolAddress((void**)&pk, g_k);
    cudaGetSymbolAddress((void**)&pv, g_v);
    cudaGetSymbolAddress((void**)&px, g_x);
    cudaGetSymbolAddress((void**)&pq, g_q);
    cudaGetSymbolAddress((void**)&ih, g_ih);
    cudaGetSymbolAddress((void**)&il, g_il);
    cudaGetSymbolAddress((void**)&ch, g_ch);
    cudaGetSymbolAddress((void**)&cl, g_cl);
    cudaGetSymbolAddress((void**)&xh, g_xh);
    cudaGetSymbolAddress((void**)&xl, g_xl);
    cudaGetSymbolAddress((void**)&wh, g_wh);
    cudaGetSymbolAddress((void**)&wl, g_wl);

    cudaFuncSetAttribute(hgemm<1,32>, cudaFuncAttributeMaxDynamicSharedMemorySize, SMEMDYN);
    cudaFuncSetAttribute(hgemm_kv,    cudaFuncAttributeMaxDynamicSharedMemorySize, SMEMDYN);
    cudaFuncSetAttribute(hgemm<0,16>, cudaFuncAttributeMaxDynamicSharedMemorySize, SMEMDYN);

    // 1) split weights (single launch) + 2) split input
    split_w5<<<(W_TOTAL + 255) / 256, 256>>>(conv_w, k_w, q_w, v_w, mlp_w);
    split_xin<<<NB * CIN * HWP / 256, 256>>>(x_in);

    const dim3 gq(TT / 128, CO / 128, NB);     // conv/q/mlp GEMMs
    const dim3 gkv(HWP / 128, 8, NB);          // fused k+v GEMM

    // 3) k+v fused projection
    hgemm_kv<<<gkv, 256, SMEMDYN>>>(ih, il,
        wh + OFF_K, wl + OFF_K, k_b, pk,
        wh + OFF_V, wl + OFF_V, v_b, pv, HWP);

    // 4) patchify conv (K-major im2col) -> staging, 5) channel LN -> x_out
    hgemm<1,32><<<gq, 256, SMEMDYN>>>(ch, cl, wh + OFF_CONV, wl + OFF_CONV, conv_b, pq, TT);
    ln_kernel<<<NB * TT, 128>>>(pq, px, xh, xl, lnc_g, lnc_b, 0);

    // 6+) iterative grouping (launch #6 = q GEMM for ncu -s 5 -c 1)
    for (int it = 0; it < ITERS; it++) {
        hgemm<0,16><<<gq, 256, SMEMDYN>>>(xh, xl, wh + OFF_Q, wl + OFF_Q, q_b, pq, TT);
        att_kernel<<<NB * TT, 128>>>(pq, pk, pv, px, xh, xl, lnv_g, lnv_b);
        hgemm<0,16><<<gq, 256, SMEMDYN>>>(xh, xl, wh + OFF_MLP, wl + OFF_MLP, mlp_b, pq, TT);
        ln_kernel<<<NB * TT, 128>>>(pq, px, xh, xl, lnm_g, lnm_b, 1);
    }

    // final transpose to NCHW
    transpose_kernel<<<dim3(TT / 32, CO / 32, NB), dim3(32, 8)>>>(px, out);
}

// round 8
// speedup vs baseline: 3.3031x; 1.2913x over previous
#include <cuda_runtime.h>
#include <cuda_fp16.h>
#include <cstdint>

// Problem constants
#define NB   4
#define CIN  256
#define HH   128
#define WW   128
#define HWP  (HH*WW)      // 16384
#define CO   512
#define TT   4096         // 64*64 output pixels
#define EPSF 1e-5f
#define ITERS 3

// ---------------------------------------------------------------------------
// Scratch
// ---------------------------------------------------------------------------
__device__ float g_x[(size_t)NB*TT*CO];    // x_out, (B,T,CO) fp32
__device__ float g_q[(size_t)NB*TT*CO];    // staging: conv/qk/upd/mlp outputs

// fp16 split operands
__device__ __align__(16) __half g_ch[(size_t)NB*1024*TT];   // im2col x_in hi [b][c*4+w][t]
__device__ __align__(16) __half g_cl[(size_t)NB*1024*TT];   // im2col lo
__device__ __align__(16) __half g_xph[(size_t)NB*HWP*CIN];  // x_in hi, pixel-major [b][pix][c]
__device__ __align__(16) __half g_xpl[(size_t)NB*HWP*CIN];  // x_in lo
__device__ __align__(16) __half g_xh[(size_t)NB*TT*CO];     // x_out hi, M-major [b][t][c]
__device__ __align__(16) __half g_xl[(size_t)NB*TT*CO];     // x_out lo
__device__ __align__(16) __half g_yh[(size_t)NB*TT*CIN];    // y hi, [b][t][j]
__device__ __align__(16) __half g_yl[(size_t)NB*TT*CIN];    // y lo
// weights: conv | v | mlp  ([n][k] row-major, k contiguous)
#define OFF_CONV 0
#define OFF_V    (512*1024)
#define OFF_MLP  (OFF_V + 512*256)
#define W_TOTAL  (OFF_MLP + 512*512)
__device__ __align__(16) __half g_wh[W_TOTAL];
__device__ __align__(16) __half g_wl[W_TOTAL];
// W2 = K_w^T Q_w (256 x 512) split, + c = K_w^T q_b
__device__ __align__(16) __half g_w2h[256*512];
__device__ __align__(16) __half g_w2l[256*512];
__device__ float g_cvec[256];

// ===========================================================================
// helpers
// ===========================================================================
__device__ __forceinline__ uint32_t smem_to_u32(const void* p) {
    uint32_t a;
    asm("{ .reg .u64 t; cvta.to.shared.u64 t, %1; cvt.u32.u64 %0, t; }"
        : "=r"(a) : "l"(p));
    return a;
}
__device__ __forceinline__ float warp_sum(float v) {
#pragma unroll
    for (int o = 16; o > 0; o >>= 1) v += __shfl_xor_sync(0xffffffffu, v, o);
    return v;
}
__device__ __forceinline__ void mma16816(float* c, const uint32_t* a, const uint32_t* b) {
    asm("mma.sync.aligned.m16n8k16.row.col.f32.f16.f16.f32 "
        "{%0,%1,%2,%3}, {%4,%5,%6,%7}, {%8,%9}, {%0,%1,%2,%3};"
        : "+f"(c[0]), "+f"(c[1]), "+f"(c[2]), "+f"(c[3])
        : "r"(a[0]), "r"(a[1]), "r"(a[2]), "r"(a[3]), "r"(b[0]), "r"(b[1]));
}
__device__ __forceinline__ void ldsm4(uint32_t* r, uint32_t a) {
    asm("ldmatrix.sync.aligned.m8n8.x4.shared.b16 {%0,%1,%2,%3}, [%4];"
        : "=r"(r[0]), "=r"(r[1]), "=r"(r[2]), "=r"(r[3]) : "r"(a) : "memory");
}
__device__ __forceinline__ void ldsm4t(uint32_t* r, uint32_t a) {
    asm("ldmatrix.sync.aligned.m8n8.x4.trans.shared.b16 {%0,%1,%2,%3}, [%4];"
        : "=r"(r[0]), "=r"(r[1]), "=r"(r[2]), "=r"(r[3]) : "r"(a) : "memory");
}
__device__ __forceinline__ void cp16(uint32_t sm, const void* g) {
    asm volatile("cp.async.cg.shared.global [%0], [%1], 16;"
        :: "r"(sm), "l"(g) : "memory");
}
__device__ __forceinline__ void cp_commit() {
    asm volatile("cp.async.commit_group;" ::: "memory");
}
template<int N> __device__ __forceinline__ void cp_wait() {
    asm volatile("cp.async.wait_group %0;" :: "n"(N) : "memory");
}
__device__ __forceinline__ void split1f(float x, __half& h, __half& l) {
    h = __float2half_rn(x);
    l = __float2half_rn(x - __half2float(h));
}
__device__ __forceinline__ void split4f(float4 f, uint2& H, uint2& L) {
    __half h[4], l[4];
    split1f(f.x, h[0], l[0]); split1f(f.y, h[1], l[1]);
    split1f(f.z, h[2], l[2]); split1f(f.w, h[3], l[3]);
    __half2 h0 = __halves2half2(h[0], h[1]), h1 = __halves2half2(h[2], h[3]);
    __half2 l0 = __halves2half2(l[0], l[1]), l1 = __halves2half2(l[2], l[3]);
    H.x = *(uint32_t*)&h0; H.y = *(uint32_t*)&h1;
    L.x = *(uint32_t*)&l0; L.y = *(uint32_t*)&l1;
}

// ===========================================================================
// setup kernels
// ===========================================================================
__global__ __launch_bounds__(256)
void split_w3(const float* __restrict__ w0, const float* __restrict__ w1,
              const float* __restrict__ w2)
{
    int i = blockIdx.x * 256 + threadIdx.x;
    if (i >= W_TOTAL) return;
    const float* s; int off;
    if      (i < OFF_V)   { s = w0; off = i; }
    else if (i < OFF_MLP) { s = w1; off = i - OFF_V; }
    else                  { s = w2; off = i - OFF_MLP; }
    __half h, l; split1f(s[off], h, l);
    g_wh[i] = h; g_wl[i] = l;
}

// x_in (NCHW) -> pixel-major fp16 hi/lo + im2col fp16 hi/lo, one pass.
// grid (HWP/32, CIN/64, NB), block 256
__global__ __launch_bounds__(256)
void split_xp(const float* __restrict__ x)
{
    __shared__ float sm[64][33];
    const int p0 = blockIdx.x * 32;
    const int c0 = blockIdx.y * 64;
    const int b  = blockIdx.z;
    const float* xb = x + ((size_t)b * CIN + c0) * HWP + p0;
    const int tx = threadIdx.x & 31, ty = threadIdx.x >> 5;   // 32 x 8
#pragma unroll
    for (int cc = ty; cc < 64; cc += 8)
        sm[cc][tx] = xb[(size_t)cc * HWP + tx];
    __syncthreads();
    // phase A: pixel-major split (coalesced u32 writes along channels)
    {
        const int cp = tx, pg = ty;
#pragma unroll
        for (int p = pg; p < 32; p += 8) {
            float f0 = sm[2 * cp][p], f1 = sm[2 * cp + 1][p];
            __half h0, l0, h1, l1; split1f(f0, h0, l0); split1f(f1, h1, l1);
            __half2 H = __halves2half2(h0, h1), L = __halves2half2(l0, l1);
            size_t o = ((size_t)b * HWP + p0 + p) * CIN + c0;
            ((uint32_t*)(g_xph + o))[cp] = *(uint32_t*)&H;
            ((uint32_t*)(g_xpl + o))[cp] = *(uint32_t*)&L;
        }
    }
    // phase B: im2col split (32 pixels are one contiguous span within row hr)
    {
        const int hr = p0 >> 7, wc0 = p0 & 127;
        const int tb = (hr >> 1) * 64 + (wc0 >> 1);
        const int whi = (hr & 1) * 2;
        const int cc = threadIdx.x >> 2, tq = threadIdx.x & 3;
        const size_t kgbase = ((size_t)b * 1024 + (size_t)(c0 + cc) * 4 + whi) * TT;
#pragma unroll
        for (int i = 0; i < 4; ++i) {
            int pp = tq + i * 4;                 // pixel-pair index 0..15
            float fe = sm[cc][2 * pp], fo = sm[cc][2 * pp + 1];
            __half he, le, hh, lh; split1f(fe, he, le); split1f(fo, hh, lh);
            int t = tb + pp;
            g_ch[kgbase + t] = he;       g_cl[kgbase + t] = le;
            g_ch[kgbase + TT + t] = hh;  g_cl[kgbase + TT + t] = lh;
        }
    }
}

// W2[j][f] = sum_o K_w[o][j] * Q_w[o][f]  (j<256, f<512), split to fp16 hi/lo.
// Also c[j] = sum_o K_w[o][j] * q_b[o] (blocks with f-tile 0).
// grid (8, 16), block 256 (16x16, 2x2 micro)
__global__ __launch_bounds__(256)
void w2_kernel(const float* __restrict__ Kw, const float* __restrict__ Qw,
               const float* __restrict__ qb)
{
    __shared__ float Ks[32][33], Qs[32][33];
    const int j0 = blockIdx.x * 32, f0 = blockIdx.y * 32;
    const int txx = threadIdx.x & 15, tyy = threadIdx.x >> 4;
    float acc[2][2] = {{0.f, 0.f}, {0.f, 0.f}};
    for (int o0 = 0; o0 < 512; o0 += 32) {
#pragma unroll
        for (int l = threadIdx.x; l < 1024; l += 256) {
            int oo = l >> 5, jj = l & 31;
            Ks[oo][jj] = Kw[(size_t)(o0 + oo) * 256 + j0 + jj];
            Qs[oo][jj] = Qw[(size_t)(o0 + oo) * 512 + f0 + jj];
        }
        __syncthreads();
#pragma unroll
        for (int oo = 0; oo < 32; ++oo) {
            float k0 = Ks[oo][tyy * 2], k1 = Ks[oo][tyy * 2 + 1];
            float q0 = Qs[oo][txx * 2], q1 = Qs[oo][txx * 2 + 1];
            acc[0][0] += k0 * q0; acc[0][1] += k0 * q1;
            acc[1][0] += k1 * q0; acc[1][1] += k1 * q1;
        }
        __syncthreads();
    }
#pragma unroll
    for (int a = 0; a < 2; a++)
#pragma unroll
        for (int bb = 0; bb < 2; bb++) {
            int j = j0 + tyy * 2 + a, f = f0 + txx * 2 + bb;
            __half h, l; split1f(acc[a][bb], h, l);
            g_w2h[(size_t)j * 512 + f] = h;
            g_w2l[(size_t)j * 512 + f] = l;
        }
    if (blockIdx.y == 0 && threadIdx.x < 32) {
        int j = j0 + threadIdx.x;
        float s = 0.f;
        for (int o = 0; o < 512; ++o) s += Kw[(size_t)o * 256 + j] * qb[o];
        g_cvec[j] = s;
    }
}

// ===========================================================================
// HMMA split-fp16 GEMM core (tile 128x128, K-chunk 32, 8 warps 2x4,
// warp tile 64x32, 3-stage cp.async, term-major MMAs)
// ===========================================================================
#define STAGE   32768
#define SMEMDYN (3*STAGE)

template<int KMAJOR, int K>
__device__ __forceinline__ void gemm_issue(
    uint32_t sb, int s, int c, int tid, int m0, int n0, int M,
    const __half* pAh, const __half* pAl,
    const __half* Bh, const __half* Bl)
{
    const int k0 = c * 32;
    const uint32_t As = sb + s * STAGE;
    const uint32_t Bs = As + 16384;
    if (KMAJOR) {
#pragma unroll
        for (int j = 0; j < 2; j++) {
            int idx = tid + j * 256;
            int r = idx >> 4, ch = idx & 15;
            uint32_t so = r * 256 + ((ch ^ (r & 7)) << 4);
            size_t go = (size_t)(k0 + r) * M + m0 + ch * 8;
            cp16(As + so, pAh + go);
            cp16(As + 8192 + so, pAl + go);
        }
    } else {
#pragma unroll
        for (int j = 0; j < 4; j++) {
            int idx = tid + j * 256;
            int r = idx >> 3, q = idx & 7;
            uint32_t sm = As + r * 128 + ((q ^ (r & 7)) << 4);
            const __half* g = ((q < 4) ? pAh : pAl)
                              + (size_t)(m0 + r) * K + k0 + (q & 3) * 8;
            cp16(sm, g);
        }
    }
#pragma unroll
    for (int j = 0; j < 4; j++) {
        int idx = tid + j * 256;
        int r = idx >> 3, q = idx & 7;
        uint32_t sm = Bs + r * 128 + ((q ^ (r & 7)) << 4);
        const __half* g = ((q < 4) ? Bh : Bl)
                          + (size_t)(n0 + r) * K + k0 + (q & 3) * 8;
        cp16(sm, g);
    }
    cp_commit();
}

template<int KMAJOR>
__device__ __forceinline__ void gemm_compute(
    uint32_t sb, int s, int lane, int wm, int wn, float acc[4][4][4])
{
    const uint32_t As = sb + s * STAGE;
    const uint32_t Bs = As + 16384;
    const int g = lane >> 3;
    const uint32_t l7 = lane & 7;
#pragma unroll
    for (int ks = 0; ks < 2; ++ks) {
        uint32_t bh[8], bl[8], ah[16], al[16];
        {
            uint32_t nrow = wn * 32 + (g >> 1) * 8 + l7;
            uint32_t cH = ((ks * 2 + (g & 1)) ^ l7) << 4;
            uint32_t cL = ((ks * 2 + (g & 1) + 4) ^ l7) << 4;
            uint32_t r0 = Bs + nrow * 128;
            ldsm4(&bh[0], r0 + cH);
            ldsm4(&bl[0], r0 + cL);
            uint32_t r1 = r0 + 16 * 128;
            ldsm4(&bh[4], r1 + cH);
            ldsm4(&bl[4], r1 + cL);
        }
#pragma unroll
        for (int mt = 0; mt < 4; ++mt) {
            if (KMAJOR) {
                uint32_t krow = ks * 16 + (g >> 1) * 8 + l7;
                uint32_t mch = wm * 8 + mt * 2 + (g & 1);
                uint32_t a = As + krow * 256 + ((mch ^ l7) << 4);
                ldsm4t(&ah[mt * 4], a);
                ldsm4t(&al[mt * 4], a + 8192);
            } else {
                uint32_t mrow = wm * 64 + mt * 16 + (g & 1) * 8 + l7;
                uint32_t ch = ks * 2 + (g >> 1);
                uint32_t ra = As + mrow * 128;
                ldsm4(&ah[mt * 4], ra + ((ch ^ l7) << 4));
                ldsm4(&al[mt * 4], ra + (((ch + 4) ^ l7) << 4));
            }
        }
#pragma unroll
        for (int mt = 0; mt < 4; ++mt)
#pragma unroll
            for (int nt = 0; nt < 4; ++nt) mma16816(acc[mt][nt], &ah[mt * 4], &bh[nt * 2]);
#pragma unroll
        for (int mt = 0; mt < 4; ++mt)
#pragma unroll
            for (int nt = 0; nt < 4; ++nt) mma16816(acc[mt][nt], &ah[mt * 4], &bl[nt * 2]);
#pragma unroll
        for (int mt = 0; mt < 4; ++mt)
#pragma unroll
            for (int nt = 0; nt < 4; ++nt) mma16816(acc[mt][nt], &al[mt * 4], &bh[nt * 2]);
    }
}

__device__ __forceinline__ void gemm_epilogue(
    float acc[4][4][4], const float* bias, float* C,
    int lane, int wm, int wn, int m0, int n0, size_t bM, int ldc)
{
    const int gq = lane >> 2, tq = lane & 3;
#pragma unroll
    for (int mt = 0; mt < 4; ++mt) {
        int mrow = m0 + wm * 64 + mt * 16 + gq;
        float* Cr = C + (bM + mrow) * ldc + n0;
#pragma unroll
        for (int nt = 0; nt < 4; ++nt) {
            int col = wn * 32 + nt * 8 + tq * 2;
            float b0 = bias[n0 + col], b1 = bias[n0 + col + 1];
            float2 v0; v0.x = acc[mt][nt][0] + b0; v0.y = acc[mt][nt][1] + b1;
            *(float2*)&Cr[col] = v0;
            float2 v1; v1.x = acc[mt][nt][2] + b0; v1.y = acc[mt][nt][3] + b1;
            *(float2*)&Cr[col + 8 * ldc] = v1;
        }
    }
}

template<int KMAJOR, int NCH>
__global__ __launch_bounds__(256, 2)
void hgemm(const __half* __restrict__ Ah, const __half* __restrict__ Al,
           const __half* __restrict__ Bh, const __half* __restrict__ Bl,
           const float* __restrict__ bias, float* __restrict__ C,
           int M, int ldc)
{
    constexpr int K = NCH * 32;
    extern __shared__ char sm_[];
    const uint32_t sb = smem_to_u32(sm_);
    const int tid = threadIdx.x;
    const int lane = tid & 31;
    const int wid = tid >> 5;
    const int wm = wid & 1, wn = wid >> 1;
    const int m0 = blockIdx.x * 128, n0 = blockIdx.y * 128, bz = blockIdx.z;
    const __half* pAh = Ah + (size_t)bz * M * K;
    const __half* pAl = Al + (size_t)bz * M * K;

    float acc[4][4][4];
#pragma unroll
    for (int i = 0; i < 4; i++)
#pragma unroll
        for (int j = 0; j < 4; j++)
#pragma unroll
            for (int r = 0; r < 4; r++) acc[i][j][r] = 0.f;

    gemm_issue<KMAJOR, K>(sb, 0, 0, tid, m0, n0, M, pAh, pAl, Bh, Bl);
    gemm_issue<KMAJOR, K>(sb, 1, 1, tid, m0, n0, M, pAh, pAl, Bh, Bl);
#pragma unroll
    for (int c = 0; c < NCH; ++c) {
        if (c < NCH - 1) cp_wait<1>(); else cp_wait<0>();
        __syncthreads();
        if (c + 2 < NCH) gemm_issue<KMAJOR, K>(sb, (c + 2) % 3, c + 2, tid, m0, n0, M, pAh, pAl, Bh, Bl);
        gemm_compute<KMAJOR>(sb, c % 3, lane, wm, wn, acc);
    }
    gemm_epilogue(acc, bias, C, lane, wm, wn, m0, n0, (size_t)bz * M, ldc);
}

// ---------------------------------------------------------------------------
// Channel LayerNorm over CO=512, float4-vectorized, 128 threads/row.
// Also emits fp16 hi/lo of the result row.
// ---------------------------------------------------------------------------
__global__ __launch_bounds__(128)
void ln_kernel(const float* __restrict__ in, float* __restrict__ xo,
               __half* __restrict__ xh, __half* __restrict__ xl,
               const float* __restrict__ g, const float* __restrict__ bvec, int add)
{
    const int tid = threadIdx.x;
    const size_t row = blockIdx.x;
    float4 v = ((const float4*)(in + row * CO))[tid];
    float s  = v.x + v.y + v.z + v.w;
    float s2 = v.x * v.x + v.y * v.y + v.z * v.z + v.w * v.w;
    s  = warp_sum(s);
    s2 = warp_sum(s2);
    __shared__ float r1[4], r2[4];
    const int lane = tid & 31, warp = tid >> 5;
    if (lane == 0) { r1[warp] = s; r2[warp] = s2; }
    __syncthreads();
    float ss = r1[0] + r1[1] + r1[2] + r1[3];
    float sq = r2[0] + r2[1] + r2[2] + r2[3];
    float mu  = ss / CO;
    float var = sq / CO - mu * mu;
    float rs  = rsqrtf(var + EPSF);
    float4 g4 = ((const float4*)g)[tid];
    float4 b4 = ((const float4*)bvec)[tid];
    float4 f;
    f.x = (v.x - mu) * rs * g4.x + b4.x;
    f.y = (v.y - mu) * rs * g4.y + b4.y;
    f.z = (v.z - mu) * rs * g4.z + b4.z;
    f.w = (v.w - mu) * rs * g4.w + b4.w;
    float4* xr = (float4*)(xo + row * CO);
    if (add) {
        float4 o = xr[tid];
        f.x += o.x; f.y += o.y; f.z += o.z; f.w += o.w;
    }
    xr[tid] = f;
    uint2 H, L; split4f(f, H, L);
    ((uint2*)(xh + row * CO))[tid] = H;
    ((uint2*)(xl + row * CO))[tid] = L;
}

// ---------------------------------------------------------------------------
// Attention core: per (b,t): logits = x_in[pix_w]·qk[t], softmax over 4
// windows, y[t] = Σ_w att_w · x_in[pix_w] (256-dim), emitted as fp16 hi/lo.
// 128 threads, thread handles 2 channels of 256.
// ---------------------------------------------------------------------------
__global__ __launch_bounds__(128)
void att2_kernel(const float* __restrict__ qk,
                 const __half* __restrict__ xph, const __half* __restrict__ xpl,
                 __half* __restrict__ yh, __half* __restrict__ yl)
{
    const int tid = threadIdx.x;
    const int row = blockIdx.x;            // b*T + t
    const int b = row >> 12;
    const int t = row & (TT - 1);
    const int ho = t >> 6, wo = t & 63;
    const int pix0 = (ho << 1) * WW + (wo << 1);
    const size_t base = ((size_t)b * HWP + pix0) * CIN + 2 * tid;

    const float2 q2 = ((const float2*)(qk + (size_t)row * 256))[tid];

    float x0[4], x1[4];
    const size_t offs0 = 0, offs1 = CIN,
                 offs2 = (size_t)WW * CIN, offs3 = (size_t)WW * CIN + CIN;
    const size_t offs[4] = {offs0, offs1, offs2, offs3};
#pragma unroll
    for (int w = 0; w < 4; ++w) {
        uint32_t H = *(const uint32_t*)(xph + base + offs[w]);
        uint32_t L = *(const uint32_t*)(xpl + base + offs[w]);
        __half2 h = *(__half2*)&H, l = *(__half2*)&L;
        x0[w] = __half2float(__low2half(h))  + __half2float(__low2half(l));
        x1[w] = __half2float(__high2half(h)) + __half2float(__high2half(l));
    }
    float d0 = q2.x * x0[0] + q2.y * x1[0];
    float d1 = q2.x * x0[1] + q2.y * x1[1];
    float d2 = q2.x * x0[2] + q2.y * x1[2];
    float d3 = q2.x * x0[3] + q2.y * x1[3];
    d0 = warp_sum(d0); d1 = warp_sum(d1); d2 = warp_sum(d2); d3 = warp_sum(d3);

    __shared__ float red[4][4];
    const int lane = tid & 31, warp = tid >> 5;
    if (lane == 0) { red[0][warp] = d0; red[1][warp] = d1;
                     red[2][warp] = d2; red[3][warp] = d3; }
    __syncthreads();
    float a0 = red[0][0] + red[0][1] + red[0][2] + red[0][3];
    float a1 = red[1][0] + red[1][1] + red[1][2] + red[1][3];
    float a2 = red[2][0] + red[2][1] + red[2][2] + red[2][3];
    float a3 = red[3][0] + red[3][1] + red[3][2] + red[3][3];
    float mx = fmaxf(fmaxf(a0, a1), fmaxf(a2, a3));
    float e0 = __expf(a0 - mx), e1 = __expf(a1 - mx);
    float e2 = __expf(a2 - mx), e3 = __expf(a3 - mx);
    float inv = 1.f / (e0 + e1 + e2 + e3);
    e0 *= inv; e1 *= inv; e2 *= inv; e3 *= inv;

    float y0 = e0 * x0[0] + e1 * x0[1] + e2 * x0[2] + e3 * x0[3];
    float y1 = e0 * x1[0] + e1 * x1[1] + e2 * x1[2] + e3 * x1[3];
    __half h0, l0, h1, l1; split1f(y0, h0, l0); split1f(y1, h1, l1);
    __half2 H = __halves2half2(h0, h1), L = __halves2half2(l0, l1);
    *(uint32_t*)(yh + (size_t)row * 256 + 2 * tid) = *(uint32_t*)&H;
    *(uint32_t*)(yl + (size_t)row * 256 + 2 * tid) = *(uint32_t*)&L;
}

// ---------------------------------------------------------------------------
// Final transpose (B,T,CO) pixel-major -> NCHW output (B,CO,64,64)
// ---------------------------------------------------------------------------
__global__ void transpose_kernel(const float* __restrict__ x, float* __restrict__ out)
{
    __shared__ float tile[32][33];
    const int b  = blockIdx.z;
    const int t0 = blockIdx.x * 32;
    const int f0 = blockIdx.y * 32;
    const int tx = threadIdx.x, ty = threadIdx.y;
#pragma unroll
    for (int j = 0; j < 32; j += 8)
        tile[ty + j][tx] = x[((size_t)b * TT + t0 + ty + j) * CO + f0 + tx];
    __syncthreads();
#pragma unroll
    for (int j = 0; j < 32; j += 8)
        out[((size_t)b * CO + f0 + ty + j) * TT + t0 + tx] = tile[tx][ty + j];
}

// ---------------------------------------------------------------------------
extern "C" void kernel_launch(void* const* d_in, const int* in_sizes, int n_in,
                              void* d_out, int out_size)
{
    const float* x_in   = (const float*)d_in[0];
    const float* conv_w = (const float*)d_in[1];
    const float* conv_b = (const float*)d_in[2];
    const float* k_w    = (const float*)d_in[3];
    const float* k_b    = (const float*)d_in[4];   // const over window -> drops in softmax
    const float* q_w    = (const float*)d_in[5];
    const float* q_b    = (const float*)d_in[6];
    const float* v_w    = (const float*)d_in[7];
    const float* v_b    = (const float*)d_in[8];
    const float* mlp_w  = (const float*)d_in[9];
    const float* mlp_b  = (const float*)d_in[10];
    const float* lnc_g  = (const float*)d_in[11];
    const float* lnc_b  = (const float*)d_in[12];
    const float* lnv_g  = (const float*)d_in[13];
    const float* lnv_b  = (const float*)d_in[14];
    const float* lnm_g  = (const float*)d_in[15];
    const float* lnm_b  = (const float*)d_in[16];
    float* out = (float*)d_out;
    (void)k_b;

    float *px, *pq;
    __half *ch, *cl, *xph, *xpl, *xh, *xl, *yh, *yl, *wh, *wl, *w2h, *w2l;
    float *cvec;
    cudaGetSymbolAddress((void**)&px, g_x);
    cudaGetSymbolAddress((void**)&pq, g_q);
    cudaGetSymbolAddress((void**)&ch, g_ch);
    cudaGetSymbolAddress((void**)&cl, g_cl);
    cudaGetSymbolAddress((void**)&xph, g_xph);
    cudaGetSymbolAddress((void**)&xpl, g_xpl);
    cudaGetSymbolAddress((void**)&xh, g_xh);
    cudaGetSymbolAddress((void**)&xl, g_xl);
    cudaGetSymbolAddress((void**)&yh, g_yh);
    cudaGetSymbolAddress((void**)&yl, g_yl);
    cudaGetSymbolAddress((void**)&wh, g_wh);
    cudaGetSymbolAddress((void**)&wl, g_wl);
    cudaGetSymbolAddress((void**)&w2h, g_w2h);
    cudaGetSymbolAddress((void**)&w2l, g_w2l);
    cudaGetSymbolAddress((void**)&cvec, g_cvec);

    cudaFuncSetAttribute(hgemm<1,32>, cudaFuncAttributeMaxDynamicSharedMemorySize, SMEMDYN);
    cudaFuncSetAttribute(hgemm<0,16>, cudaFuncAttributeMaxDynamicSharedMemorySize, SMEMDYN);
    cudaFuncSetAttribute(hgemm<0,8>,  cudaFuncAttributeMaxDynamicSharedMemorySize, SMEMDYN);

    // 1) split weights  2) split+transpose input (pixel-major + im2col)
    split_w3<<<(W_TOTAL + 255) / 256, 256>>>(conv_w, v_w, mlp_w);
    split_xp<<<dim3(HWP / 32, CIN / 64, NB), 256>>>(x_in);
    // 3) W2 = K_w^T Q_w (+ c = K_w^T q_b)
    w2_kernel<<<dim3(8, 16), 256>>>(k_w, q_w, q_b);

    // 4) patchify conv -> staging, 5) channel LN -> x_out
    hgemm<1,32><<<dim3(TT / 128, 4, NB), 256, SMEMDYN>>>(
        ch, cl, wh + OFF_CONV, wl + OFF_CONV, conv_b, pq, TT, CO);
    ln_kernel<<<NB * TT, 128>>>(pq, px, xh, xl, lnc_g, lnc_b, 0);

    // 6+) iterative grouping (launch #6 = qk GEMM for ncu -s 5 -c 1)
    for (int it = 0; it < ITERS; it++) {
        // qk[t] = W2 x_out[t] + c   (M=TT, N=256, K=512) -> pq (ldc=256)
        hgemm<0,16><<<dim3(TT / 128, 2, NB), 256, SMEMDYN>>>(
            xh, xl, w2h, w2l, cvec, pq, TT, 256);
        // att: softmax(x_in·qk) over 2x2 window, y = Σ att·x_in
        att2_kernel<<<NB * TT, 128>>>(pq, xph, xpl, yh, yl);
        // upd = V_w y + v_b   (M=TT, N=512, K=256) -> pq
        hgemm<0,8><<<dim3(TT / 128, 4, NB), 256, SMEMDYN>>>(
            yh, yl, wh + OFF_V, wl + OFF_V, v_b, pq, TT, CO);
        // x += LN(upd)
        ln_kernel<<<NB * TT, 128>>>(pq, px, xh, xl, lnv_g, lnv_b, 1);
        // mlp = M_w x + mlp_b -> pq ; x += LN(mlp)
        hgemm<0,16><<<dim3(TT / 128, 4, NB), 256, SMEMDYN>>>(
            xh, xl, wh + OFF_MLP, wl + OFF_MLP, mlp_b, pq, TT, CO);
        ln_kernel<<<NB * TT, 128>>>(pq, px, xh, xl, lnm_g, lnm_b, 1);
    }

    // final transpose to NCHW
    transpose_kernel<<<dim3(TT / 32, CO / 32, NB), dim3(32, 8)>>>(px, out);
}